// round 1
// baseline (speedup 1.0000x reference)
#include <cuda_runtime.h>
#include <cuda_bf16.h>
#include <cstdint>
#include <cstdio>

// Problem constants
#define SEQ   2048
#define HDIM  2880
#define NH    64
#define HD    64
#define NKV   8
#define GROUPS 8
#define RANK  384
#define QDIM  4096   // NH*HD
#define KVDIM 1024   // NKV*HD*2
#define ROPE_BASE 150000.0f

// ---------------------------------------------------------------------------
// Scratch (module-load allocated; allowed per harness rules)
// ---------------------------------------------------------------------------
__device__ float g_q   [SEQ * QDIM];        // q projection output [S][NH*HD]
__device__ float g_ckv [SEQ * RANK];        // compressed kv        [S][RANK]
__device__ float g_kv  [SEQ * KVDIM];       // kv projection        [S][NKV*128]
__device__ float g_qt  [NH  * SEQ * HD];    // q roped, [NH][S][HD]
__device__ float g_kt  [NKV * SEQ * HD];    // k roped, [NKV][S][HD]
__device__ float g_vt  [NKV * SEQ * HD];    // v,       [NKV][S][HD]
__device__ float g_attn[SEQ * QDIM];        // attention output [S][NH*HD]

// ---------------------------------------------------------------------------
// SGEMM: C[M,N] = A[M,K] @ B[N,K]^T (+ bias[N])
// 128x128 tile, BK=8, 256 threads, 8x8 per-thread register tile.
// ---------------------------------------------------------------------------
__global__ __launch_bounds__(256)
void sgemm_nt(const float* __restrict__ A, const float* __restrict__ B,
              const float* __restrict__ bias, float* __restrict__ C,
              int M, int N, int K) {
    __shared__ float As[8][128];
    __shared__ float Bs[8][128];

    const int tid = threadIdx.x;
    const int tx = tid & 15;          // 0..15 -> N
    const int ty = tid >> 4;          // 0..15 -> M
    const int row0 = blockIdx.y * 128;
    const int col0 = blockIdx.x * 128;

    float acc[8][8];
#pragma unroll
    for (int i = 0; i < 8; i++)
#pragma unroll
        for (int j = 0; j < 8; j++) acc[i][j] = 0.f;

    const int lm = tid >> 1;                 // 0..127 row within tile
    const int lk = (tid & 1) * 4;            // 0 or 4

    for (int k0 = 0; k0 < K; k0 += 8) {
        // load A tile (128 x 8) -> As[k][m]
        {
            int gm = row0 + lm;
            float4 v = make_float4(0.f, 0.f, 0.f, 0.f);
            if (gm < M) v = *(const float4*)(A + (size_t)gm * K + k0 + lk);
            As[lk + 0][lm] = v.x; As[lk + 1][lm] = v.y;
            As[lk + 2][lm] = v.z; As[lk + 3][lm] = v.w;
        }
        // load B tile (128 x 8) -> Bs[k][n]
        {
            int gn = col0 + lm;
            float4 v = make_float4(0.f, 0.f, 0.f, 0.f);
            if (gn < N) v = *(const float4*)(B + (size_t)gn * K + k0 + lk);
            Bs[lk + 0][lm] = v.x; Bs[lk + 1][lm] = v.y;
            Bs[lk + 2][lm] = v.z; Bs[lk + 3][lm] = v.w;
        }
        __syncthreads();

#pragma unroll
        for (int k = 0; k < 8; k++) {
            float a[8], b[8];
            float4 a0 = *(const float4*)&As[k][ty * 8];
            float4 a1 = *(const float4*)&As[k][ty * 8 + 4];
            a[0]=a0.x; a[1]=a0.y; a[2]=a0.z; a[3]=a0.w;
            a[4]=a1.x; a[5]=a1.y; a[6]=a1.z; a[7]=a1.w;
            float4 b0 = *(const float4*)&Bs[k][tx * 8];
            float4 b1 = *(const float4*)&Bs[k][tx * 8 + 4];
            b[0]=b0.x; b[1]=b0.y; b[2]=b0.z; b[3]=b0.w;
            b[4]=b1.x; b[5]=b1.y; b[6]=b1.z; b[7]=b1.w;
#pragma unroll
            for (int i = 0; i < 8; i++)
#pragma unroll
                for (int j = 0; j < 8; j++)
                    acc[i][j] = fmaf(a[i], b[j], acc[i][j]);
        }
        __syncthreads();
    }

#pragma unroll
    for (int i = 0; i < 8; i++) {
        int gm = row0 + ty * 8 + i;
        if (gm >= M) continue;
#pragma unroll
        for (int j = 0; j < 8; j++) {
            int gn = col0 + tx * 8 + j;
            if (gn < N) {
                float v = acc[i][j];
                if (bias) v += bias[gn];
                C[(size_t)gm * N + gn] = v;
            }
        }
    }
}

// ---------------------------------------------------------------------------
// RoPE helpers (mimic reference fp32 rounding: fp32 pow, fp32 pos*inv_freq)
// ---------------------------------------------------------------------------
__device__ __forceinline__ void rope_cs(int s, int d, float& c, float& sn) {
    int dd = d & 31;
    float inv = 1.0f / powf(ROPE_BASE, (float)(2 * dd) / 64.0f);
    float ang = (float)s * inv;
    c = cosf(ang);
    sn = sinf(ang);
}

// RoPE q + transpose to [NH][S][HD]
__global__ void rope_q_kernel(const float* __restrict__ q, float* __restrict__ qt) {
    int s = blockIdx.x;
    int t = threadIdx.x;                 // 256: 4 heads x 64 dims
    int h = blockIdx.y * 4 + (t >> 6);
    int d = t & 63;
    const float* row = q + (size_t)s * QDIM + h * HD;
    float v = row[d];
    float other = (d < 32) ? -row[d + 32] : row[d - 32];
    float c, sn; rope_cs(s, d, c, sn);
    qt[((size_t)h * SEQ + s) * HD + d] = v * c + other * sn;
}

// split kv, RoPE k, transpose to [NKV][S][HD]
__global__ void rope_kv_kernel(const float* __restrict__ kv,
                               float* __restrict__ kt, float* __restrict__ vt) {
    int s = blockIdx.x;
    int kh = blockIdx.y;
    int d = threadIdx.x;                 // 64
    const float* row = kv + (size_t)s * KVDIM + kh * (2 * HD);
    float kval = row[d];
    float other = (d < 32) ? -row[d + 32] : row[d - 32];
    float c, sn; rope_cs(s, d, c, sn);
    size_t o = ((size_t)kh * SEQ + s) * HD + d;
    kt[o] = kval * c + other * sn;
    vt[o] = row[HD + d];
}

// ---------------------------------------------------------------------------
// Flash attention (causal). One block = (head, 64 q rows). 256 threads.
// smem: qs natural [64][64], ksT transposed [64(d)][64(j)] (aliased by P tile
// [64(i)][64(j)] after scores), vs natural [64][64]. Exactly 48KB.
// ---------------------------------------------------------------------------
__global__ __launch_bounds__(256)
void attn_kernel(const float* __restrict__ qt, const float* __restrict__ kt,
                 const float* __restrict__ vt, float* __restrict__ out) {
    __shared__ float qs[64 * 64];
    __shared__ float ksps[64 * 64];   // K^T during scores, P after
    __shared__ float vs[64 * 64];

    const int h   = blockIdx.y;
    const int qb  = blockIdx.x;
    const int kvh = h >> 3;           // GROUPS = 8
    const int tid = threadIdx.x;
    const int tx  = tid & 15;
    const int ty  = tid >> 4;
    const int i0  = ty * 4;
    const int j0  = tx * 4;

    const float* qbase = qt + ((size_t)h * SEQ + qb * 64) * HD;
    const float* kbase = kt + (size_t)kvh * SEQ * HD;
    const float* vbase = vt + (size_t)kvh * SEQ * HD;

    // load q tile (coalesced float4)
    for (int c = tid; c < 64 * 16; c += 256) {
        int r = c >> 4, d4 = (c & 15) * 4;
        float4 v = *(const float4*)(qbase + r * 64 + d4);
        float* p = &qs[r * 64 + d4];
        p[0] = v.x; p[1] = v.y; p[2] = v.z; p[3] = v.w;
    }

    float o[4][4];
    float m[4], l[4];
#pragma unroll
    for (int i = 0; i < 4; i++) {
        m[i] = -3.0e38f; l[i] = 0.f;
#pragma unroll
        for (int j = 0; j < 4; j++) o[i][j] = 0.f;
    }

    for (int jb = 0; jb <= qb; jb++) {
        __syncthreads();
        // K tile: transpose-store ksT[d][j]. mapping: lane -> (r = c&63, d4).
        for (int c = tid; c < 64 * 16; c += 256) {
            int r = c & 63, d4 = (c >> 6) * 4;
            float4 kv4 = *(const float4*)(kbase + ((size_t)jb * 64 + r) * 64 + d4);
            ksps[(d4 + 0) * 64 + r] = kv4.x;
            ksps[(d4 + 1) * 64 + r] = kv4.y;
            ksps[(d4 + 2) * 64 + r] = kv4.z;
            ksps[(d4 + 3) * 64 + r] = kv4.w;
        }
        // V tile natural (coalesced)
        for (int c = tid; c < 64 * 16; c += 256) {
            int r = c >> 4, d4 = (c & 15) * 4;
            float4 vv4 = *(const float4*)(vbase + ((size_t)jb * 64 + r) * 64 + d4);
            float* p = &vs[r * 64 + d4];
            p[0] = vv4.x; p[1] = vv4.y; p[2] = vv4.z; p[3] = vv4.w;
        }
        __syncthreads();

        // scores s[i][j] = sum_d q[i][d] * k[j][d]
        float s[4][4];
#pragma unroll
        for (int i = 0; i < 4; i++)
#pragma unroll
            for (int j = 0; j < 4; j++) s[i][j] = 0.f;

#pragma unroll 4
        for (int d = 0; d < 64; d++) {
            float a[4];
#pragma unroll
            for (int i = 0; i < 4; i++) a[i] = qs[(i0 + i) * 64 + d];
            float4 b4 = *(const float4*)&ksps[d * 64 + j0];
            float b[4] = {b4.x, b4.y, b4.z, b4.w};
#pragma unroll
            for (int i = 0; i < 4; i++)
#pragma unroll
                for (int j = 0; j < 4; j++)
                    s[i][j] = fmaf(a[i], b[j], s[i][j]);
        }

        const bool diag = (jb == qb);
#pragma unroll
        for (int i = 0; i < 4; i++)
#pragma unroll
            for (int j = 0; j < 4; j++) {
                s[i][j] *= 0.125f;   // 1/sqrt(64)
                if (diag && (j0 + j) > (i0 + i)) s[i][j] = -3.0e38f;
            }

        // online softmax update
        float scale[4];
#pragma unroll
        for (int i = 0; i < 4; i++) {
            float v = fmaxf(fmaxf(s[i][0], s[i][1]), fmaxf(s[i][2], s[i][3]));
#pragma unroll
            for (int off = 1; off < 16; off <<= 1)
                v = fmaxf(v, __shfl_xor_sync(0xffffffffu, v, off));
            float mn = fmaxf(m[i], v);
            scale[i] = __expf(m[i] - mn);
            m[i] = mn;
            float rs = 0.f;
#pragma unroll
            for (int j = 0; j < 4; j++) {
                s[i][j] = __expf(s[i][j] - mn);
                rs += s[i][j];
            }
#pragma unroll
            for (int off = 1; off < 16; off <<= 1)
                rs += __shfl_xor_sync(0xffffffffu, rs, off);
            l[i] = l[i] * scale[i] + rs;
#pragma unroll
            for (int j = 0; j < 4; j++) o[i][j] *= scale[i];
        }

        __syncthreads();   // all reads of ksT done
        // write P into ksps as [i][j]
#pragma unroll
        for (int i = 0; i < 4; i++)
#pragma unroll
            for (int j = 0; j < 4; j++)
                ksps[(i0 + i) * 64 + (j0 + j)] = s[i][j];
        __syncthreads();

        // O += P @ V
#pragma unroll 4
        for (int j = 0; j < 64; j++) {
            float a[4];
#pragma unroll
            for (int i = 0; i < 4; i++) a[i] = ksps[(i0 + i) * 64 + j];
            float4 b4 = *(const float4*)&vs[j * 64 + j0];
            float b[4] = {b4.x, b4.y, b4.z, b4.w};
#pragma unroll
            for (int i = 0; i < 4; i++)
#pragma unroll
                for (int dd = 0; dd < 4; dd++)
                    o[i][dd] = fmaf(a[i], b[dd], o[i][dd]);
        }
    }

    // write: out[s][h*64 + d]
#pragma unroll
    for (int i = 0; i < 4; i++) {
        float inv = 1.0f / l[i];
        size_t row = (size_t)(qb * 64 + i0 + i);
#pragma unroll
        for (int dd = 0; dd < 4; dd++)
            out[row * QDIM + h * HD + j0 + dd] = o[i][dd] * inv;
    }
}

// ---------------------------------------------------------------------------
// Launch
// ---------------------------------------------------------------------------
extern "C" void kernel_launch(void* const* d_in, const int* in_sizes, int n_in,
                              void* d_out, int out_size) {
    const float* hidden = (const float*)d_in[0];
    // d_in[1] = attention_mask (pure causal; applied analytically)
    const float* q_w    = (const float*)d_in[2];
    const float* q_b    = (const float*)d_in[3];
    const float* kv_a_w = (const float*)d_in[4];
    const float* kv_b_w = (const float*)d_in[5];
    const float* o_w    = (const float*)d_in[6];
    const float* o_b    = (const float*)d_in[7];
    float* out = (float*)d_out;

    float *p_q, *p_ckv, *p_kv, *p_qt, *p_kt, *p_vt, *p_attn;
    cudaGetSymbolAddress((void**)&p_q,    g_q);
    cudaGetSymbolAddress((void**)&p_ckv,  g_ckv);
    cudaGetSymbolAddress((void**)&p_kv,   g_kv);
    cudaGetSymbolAddress((void**)&p_qt,   g_qt);
    cudaGetSymbolAddress((void**)&p_kt,   g_kt);
    cudaGetSymbolAddress((void**)&p_vt,   g_vt);
    cudaGetSymbolAddress((void**)&p_attn, g_attn);

    const int MB = SEQ / 128;  // 16

    // q projection: [S,QDIM]
    sgemm_nt<<<dim3((QDIM + 127) / 128, MB), 256>>>(hidden, q_w, q_b, p_q, SEQ, QDIM, HDIM);
    // compressed kv: [S,RANK]
    sgemm_nt<<<dim3((RANK + 127) / 128, MB), 256>>>(hidden, kv_a_w, nullptr, p_ckv, SEQ, RANK, HDIM);
    // kv expand: [S,KVDIM]
    sgemm_nt<<<dim3((KVDIM + 127) / 128, MB), 256>>>(p_ckv, kv_b_w, nullptr, p_kv, SEQ, KVDIM, RANK);
    // rope + transpose
    rope_q_kernel<<<dim3(SEQ, NH / 4), 256>>>(p_q, p_qt);
    rope_kv_kernel<<<dim3(SEQ, NKV), 64>>>(p_kv, p_kt, p_vt);
    // attention
    attn_kernel<<<dim3(SEQ / 64, NH), 256>>>(p_qt, p_kt, p_vt, p_attn);
    // output projection
    sgemm_nt<<<dim3((HDIM + 127) / 128, MB), 256>>>(p_attn, o_w, o_b, out, SEQ, HDIM, QDIM);
}

// round 2
// speedup vs baseline: 1.2196x; 1.2196x over previous
#include <cuda_runtime.h>
#include <cuda_bf16.h>
#include <mma.h>
#include <cstdint>

using namespace nvcuda;

// Problem constants
#define SEQ   2048
#define HDIM  2880
#define NH    64
#define HD    64
#define NKV   8
#define RANK  384
#define QDIM  4096   // NH*HD
#define KVDIM 1024   // NKV*HD*2
#define ROPE_BASE 150000.0f

// ---------------------------------------------------------------------------
// Scratch
// ---------------------------------------------------------------------------
__device__ float g_q   [SEQ * QDIM];
__device__ float g_ckv [SEQ * RANK];
__device__ float g_kv  [SEQ * KVDIM];
__device__ float g_qt  [NH  * SEQ * HD];
__device__ float g_kt  [NKV * SEQ * HD];
__device__ float g_vt  [NKV * SEQ * HD];
__device__ float g_attn[SEQ * QDIM];

__device__ __forceinline__ float to_tf32(float x) {
    float r;
    asm("cvt.rna.tf32.f32 %0, %1;" : "=f"(r) : "f"(x));
    return r;
}

// ---------------------------------------------------------------------------
// TF32 tensor-core GEMM: C[M,N] = A[M,K] @ B[N,K]^T
// 128x128 block tile, BK=32, 256 threads (8 warps, 2x4), warp tile 64x32.
// ---------------------------------------------------------------------------
#define BM 128
#define BN 128
#define BK 32
#define LDT (BK + 4)   // 36, mult of 4

__global__ __launch_bounds__(256, 1)
void tf32_gemm_nt(const float* __restrict__ A, const float* __restrict__ B,
                  float* __restrict__ C, int M, int N, int K) {
    __shared__ float sa[BM][LDT];
    __shared__ float sb[BN][LDT];

    const int tid  = threadIdx.x;
    const int warp = tid >> 5;
    const int wm   = warp >> 2;          // 0..1
    const int wn   = warp & 3;           // 0..3
    const int row0 = blockIdx.y * BM;
    const int col0 = blockIdx.x * BN;

    wmma::fragment<wmma::accumulator, 16, 16, 8, float> acc[4][2];
#pragma unroll
    for (int i = 0; i < 4; i++)
#pragma unroll
        for (int j = 0; j < 2; j++) wmma::fill_fragment(acc[i][j], 0.0f);

    // prefetch registers: 4 float4 per thread per matrix
    float4 pa[4], pb[4];

    auto gload_a = [&](int k0) {
#pragma unroll
        for (int i = 0; i < 4; i++) {
            int idx = tid + i * 256;
            int r = idx >> 3, c4 = (idx & 7) * 4;
            pa[i] = *(const float4*)(A + (size_t)(row0 + r) * K + k0 + c4);
        }
    };
    auto gload_b = [&](int k0) {
#pragma unroll
        for (int i = 0; i < 4; i++) {
            int idx = tid + i * 256;
            int r = idx >> 3, c4 = (idx & 7) * 4;
            int gn = col0 + r;
            pb[i] = (gn < N) ? *(const float4*)(B + (size_t)gn * K + k0 + c4)
                             : make_float4(0.f, 0.f, 0.f, 0.f);
        }
    };
    auto smem_store = [&]() {
#pragma unroll
        for (int i = 0; i < 4; i++) {
            int idx = tid + i * 256;
            int r = idx >> 3, c4 = (idx & 7) * 4;
            sa[r][c4 + 0] = to_tf32(pa[i].x); sa[r][c4 + 1] = to_tf32(pa[i].y);
            sa[r][c4 + 2] = to_tf32(pa[i].z); sa[r][c4 + 3] = to_tf32(pa[i].w);
            sb[r][c4 + 0] = to_tf32(pb[i].x); sb[r][c4 + 1] = to_tf32(pb[i].y);
            sb[r][c4 + 2] = to_tf32(pb[i].z); sb[r][c4 + 3] = to_tf32(pb[i].w);
        }
    };

    gload_a(0); gload_b(0);
    smem_store();
    __syncthreads();

    for (int k0 = BK; k0 <= K; k0 += BK) {
        bool has_next = (k0 < K);
        if (has_next) { gload_a(k0); gload_b(k0); }

#pragma unroll
        for (int kk = 0; kk < BK; kk += 8) {
            wmma::fragment<wmma::matrix_a, 16, 16, 8, wmma::precision::tf32, wmma::row_major> af[4];
            wmma::fragment<wmma::matrix_b, 16, 16, 8, wmma::precision::tf32, wmma::col_major> bf[2];
#pragma unroll
            for (int i = 0; i < 4; i++)
                wmma::load_matrix_sync(af[i], &sa[wm * 64 + i * 16][kk], LDT);
#pragma unroll
            for (int j = 0; j < 2; j++)
                wmma::load_matrix_sync(bf[j], &sb[wn * 32 + j * 16][kk], LDT);
#pragma unroll
            for (int i = 0; i < 4; i++)
#pragma unroll
                for (int j = 0; j < 2; j++)
                    wmma::mma_sync(acc[i][j], af[i], bf[j], acc[i][j]);
        }
        __syncthreads();
        if (has_next) {
            smem_store();
            __syncthreads();
        }
    }

#pragma unroll
    for (int i = 0; i < 4; i++) {
        int gm = row0 + wm * 64 + i * 16;
#pragma unroll
        for (int j = 0; j < 2; j++) {
            int gn = col0 + wn * 32 + j * 16;
            if (gn + 16 <= N)
                wmma::store_matrix_sync(C + (size_t)gm * N + gn, acc[i][j], N,
                                        wmma::mem_row_major);
        }
    }
}

// ---------------------------------------------------------------------------
// RoPE (mimics reference fp32 rounding)
// ---------------------------------------------------------------------------
__device__ __forceinline__ void rope_cs(int s, int d, float& c, float& sn) {
    int dd = d & 31;
    float inv = 1.0f / powf(ROPE_BASE, (float)(2 * dd) / 64.0f);
    float ang = (float)s * inv;
    c = cosf(ang);
    sn = sinf(ang);
}

// RoPE q (with bias) + transpose to [NH][S][HD]
__global__ void rope_q_kernel(const float* __restrict__ q, const float* __restrict__ qb,
                              float* __restrict__ qt) {
    int s = blockIdx.x;
    int t = threadIdx.x;
    int h = blockIdx.y * 4 + (t >> 6);
    int d = t & 63;
    const float* row = q + (size_t)s * QDIM + h * HD;
    const float* brow = qb + h * HD;
    float v = row[d] + brow[d];
    float other = (d < 32) ? -(row[d + 32] + brow[d + 32]) : (row[d - 32] + brow[d - 32]);
    float c, sn; rope_cs(s, d, c, sn);
    qt[((size_t)h * SEQ + s) * HD + d] = v * c + other * sn;
}

__global__ void rope_kv_kernel(const float* __restrict__ kv,
                               float* __restrict__ kt, float* __restrict__ vt) {
    int s = blockIdx.x;
    int kh = blockIdx.y;
    int d = threadIdx.x;
    const float* row = kv + (size_t)s * KVDIM + kh * (2 * HD);
    float kval = row[d];
    float other = (d < 32) ? -row[d + 32] : row[d - 32];
    float c, sn; rope_cs(s, d, c, sn);
    size_t o = ((size_t)kh * SEQ + s) * HD + d;
    kt[o] = kval * c + other * sn;
    vt[o] = row[HD + d];
}

// ---------------------------------------------------------------------------
// Flash attention with TF32 wmma. Block = (head, 64 q rows), 256 threads.
// smem: qs[64][64] Q, ks[64][64] K tile then S/P, vs[64][64] V tile then PV.
// ---------------------------------------------------------------------------
__global__ __launch_bounds__(256, 2)
void attn_wmma(const float* __restrict__ qt, const float* __restrict__ kt,
               const float* __restrict__ vt, float* __restrict__ out) {
    __shared__ float qs[64][64];
    __shared__ float ks[64][64];   // K^? tile -> S -> P
    __shared__ float vs[64][64];   // V tile -> PV staging

    const int tid  = threadIdx.x;
    const int warp = tid >> 5;
    const int wm   = warp >> 1;          // 0..3 (16-row strip)
    const int wn   = warp & 1;           // 0..1 (32-col strip)
    const int h    = blockIdx.y;
    const int qb   = gridDim.x - 1 - blockIdx.x;   // long blocks first
    const int kvh  = h >> 3;

    const float* qbase = qt + ((size_t)h * SEQ + qb * 64) * HD;
    const float* kbase = kt + (size_t)kvh * SEQ * HD;
    const float* vbase = vt + (size_t)kvh * SEQ * HD;

    // Load Q tile (tf32-converted)
#pragma unroll
    for (int i = 0; i < 4; i++) {
        int idx = tid + i * 256;
        int r = idx >> 4, c4 = (idx & 15) * 4;
        float4 v = *(const float4*)(qbase + r * 64 + c4);
        qs[r][c4 + 0] = to_tf32(v.x); qs[r][c4 + 1] = to_tf32(v.y);
        qs[r][c4 + 2] = to_tf32(v.z); qs[r][c4 + 3] = to_tf32(v.w);
    }

    // Per-thread O state: row = tid/4, cols (tid%4)*16 .. +16
    const int orow = tid >> 2;
    const int oq   = tid & 3;
    float O[16];
#pragma unroll
    for (int c = 0; c < 16; c++) O[c] = 0.f;
    float mrow = -3.0e38f, lrow = 0.f;
    const int gi = qb * 64 + orow;

    __syncthreads();

    for (int jb = 0; jb <= qb; jb++) {
        // Load K, V tiles (tf32-converted)
#pragma unroll
        for (int i = 0; i < 4; i++) {
            int idx = tid + i * 256;
            int r = idx >> 4, c4 = (idx & 15) * 4;
            float4 kv4 = *(const float4*)(kbase + ((size_t)jb * 64 + r) * 64 + c4);
            ks[r][c4 + 0] = to_tf32(kv4.x); ks[r][c4 + 1] = to_tf32(kv4.y);
            ks[r][c4 + 2] = to_tf32(kv4.z); ks[r][c4 + 3] = to_tf32(kv4.w);
            float4 vv4 = *(const float4*)(vbase + ((size_t)jb * 64 + r) * 64 + c4);
            vs[r][c4 + 0] = to_tf32(vv4.x); vs[r][c4 + 1] = to_tf32(vv4.y);
            vs[r][c4 + 2] = to_tf32(vv4.z); vs[r][c4 + 3] = to_tf32(vv4.w);
        }
        __syncthreads();

        // S = Q @ K^T  (warp computes 16x32)
        wmma::fragment<wmma::accumulator, 16, 16, 8, float> sacc[2];
        wmma::fill_fragment(sacc[0], 0.f);
        wmma::fill_fragment(sacc[1], 0.f);
#pragma unroll
        for (int kk = 0; kk < 64; kk += 8) {
            wmma::fragment<wmma::matrix_a, 16, 16, 8, wmma::precision::tf32, wmma::row_major> af;
            wmma::load_matrix_sync(af, &qs[wm * 16][kk], 64);
#pragma unroll
            for (int j = 0; j < 2; j++) {
                wmma::fragment<wmma::matrix_b, 16, 16, 8, wmma::precision::tf32, wmma::col_major> bf;
                wmma::load_matrix_sync(bf, &ks[wn * 32 + j * 16][kk], 64);
                wmma::mma_sync(sacc[j], af, bf, sacc[j]);
            }
        }
        __syncthreads();   // all warps done reading K tile
#pragma unroll
        for (int j = 0; j < 2; j++)
            wmma::store_matrix_sync(&ks[wm * 16][wn * 32 + j * 16], sacc[j], 64,
                                    wmma::mem_row_major);
        __syncthreads();

        // Online softmax (SIMT): thread owns row=orow, 16 cols
        const bool diag = (jb == qb);
        const int gj0 = jb * 64;
        float p[16];
        float lmax = -3.0e38f;
#pragma unroll
        for (int c = 0; c < 16; c++) {
            int j = oq * 16 + c;
            float sv = ks[orow][j] * 0.125f;   // 1/sqrt(64)
            if (diag && (gj0 + j) > gi) sv = -3.0e38f;
            p[c] = sv;
            lmax = fmaxf(lmax, sv);
        }
        lmax = fmaxf(lmax, __shfl_xor_sync(0xffffffffu, lmax, 1));
        lmax = fmaxf(lmax, __shfl_xor_sync(0xffffffffu, lmax, 2));
        float mnew  = fmaxf(mrow, lmax);
        float scale = __expf(mrow - mnew);
        float rs = 0.f;
#pragma unroll
        for (int c = 0; c < 16; c++) {
            p[c] = __expf(p[c] - mnew);
            rs += p[c];
        }
        rs += __shfl_xor_sync(0xffffffffu, rs, 1);
        rs += __shfl_xor_sync(0xffffffffu, rs, 2);
        lrow = lrow * scale + rs;
        mrow = mnew;
#pragma unroll
        for (int c = 0; c < 16; c++) O[c] *= scale;
        // write P (tf32) back into ks
#pragma unroll
        for (int c = 0; c < 16; c++) ks[orow][oq * 16 + c] = to_tf32(p[c]);
        __syncthreads();

        // PV = P @ V  (warp computes 16x32)
        wmma::fragment<wmma::accumulator, 16, 16, 8, float> pvacc[2];
        wmma::fill_fragment(pvacc[0], 0.f);
        wmma::fill_fragment(pvacc[1], 0.f);
#pragma unroll
        for (int kk = 0; kk < 64; kk += 8) {
            wmma::fragment<wmma::matrix_a, 16, 16, 8, wmma::precision::tf32, wmma::row_major> af;
            wmma::load_matrix_sync(af, &ks[wm * 16][kk], 64);
#pragma unroll
            for (int j = 0; j < 2; j++) {
                wmma::fragment<wmma::matrix_b, 16, 16, 8, wmma::precision::tf32, wmma::row_major> bf;
                wmma::load_matrix_sync(bf, &vs[kk][wn * 32 + j * 16], 64);
                wmma::mma_sync(pvacc[j], af, bf, pvacc[j]);
            }
        }
        __syncthreads();   // all warps done reading V tile
#pragma unroll
        for (int j = 0; j < 2; j++)
            wmma::store_matrix_sync(&vs[wm * 16][wn * 32 + j * 16], pvacc[j], 64,
                                    wmma::mem_row_major);
        __syncthreads();

        // Accumulate into O registers
#pragma unroll
        for (int c = 0; c < 16; c++) O[c] += vs[orow][oq * 16 + c];
        __syncthreads();   // before next iteration overwrites ks/vs
    }

    // Write out[s][h*64 + d]
    float inv = 1.0f / lrow;
    size_t row = (size_t)(qb * 64 + orow);
    float* dst = out + row * QDIM + h * HD + oq * 16;
#pragma unroll
    for (int c4 = 0; c4 < 4; c4++) {
        float4 v = make_float4(O[c4 * 4 + 0] * inv, O[c4 * 4 + 1] * inv,
                               O[c4 * 4 + 2] * inv, O[c4 * 4 + 3] * inv);
        *(float4*)(dst + c4 * 4) = v;
    }
}

// ---------------------------------------------------------------------------
// Bias add for final output: out[s][n] += o_b[n]
// ---------------------------------------------------------------------------
__global__ void add_bias_kernel(float* __restrict__ C, const float* __restrict__ b, int N) {
    int s = blockIdx.x;
    for (int c4 = threadIdx.x * 4; c4 < N; c4 += blockDim.x * 4) {
        float4 v = *(float4*)(C + (size_t)s * N + c4);
        float4 bb = *(const float4*)(b + c4);
        v.x += bb.x; v.y += bb.y; v.z += bb.z; v.w += bb.w;
        *(float4*)(C + (size_t)s * N + c4) = v;
    }
}

// ---------------------------------------------------------------------------
// Launch
// ---------------------------------------------------------------------------
extern "C" void kernel_launch(void* const* d_in, const int* in_sizes, int n_in,
                              void* d_out, int out_size) {
    const float* hidden = (const float*)d_in[0];
    const float* q_w    = (const float*)d_in[2];
    const float* q_b    = (const float*)d_in[3];
    const float* kv_a_w = (const float*)d_in[4];
    const float* kv_b_w = (const float*)d_in[5];
    const float* o_w    = (const float*)d_in[6];
    const float* o_b    = (const float*)d_in[7];
    float* out = (float*)d_out;

    float *p_q, *p_ckv, *p_kv, *p_qt, *p_kt, *p_vt, *p_attn;
    cudaGetSymbolAddress((void**)&p_q,    g_q);
    cudaGetSymbolAddress((void**)&p_ckv,  g_ckv);
    cudaGetSymbolAddress((void**)&p_kv,   g_kv);
    cudaGetSymbolAddress((void**)&p_qt,   g_qt);
    cudaGetSymbolAddress((void**)&p_kt,   g_kt);
    cudaGetSymbolAddress((void**)&p_vt,   g_vt);
    cudaGetSymbolAddress((void**)&p_attn, g_attn);

    const int MB = SEQ / 128;  // 16

    // q projection: [S,QDIM] = hidden @ q_w^T
    tf32_gemm_nt<<<dim3(QDIM / 128, MB), 256>>>(hidden, q_w, p_q, SEQ, QDIM, HDIM);
    // compressed kv: [S,RANK]
    tf32_gemm_nt<<<dim3(RANK / 128, MB), 256>>>(hidden, kv_a_w, p_ckv, SEQ, RANK, HDIM);
    // kv expand: [S,KVDIM]
    tf32_gemm_nt<<<dim3(KVDIM / 128, MB), 256>>>(p_ckv, kv_b_w, p_kv, SEQ, KVDIM, RANK);
    // rope + transpose
    rope_q_kernel<<<dim3(SEQ, NH / 4), 256>>>(p_q, q_b, p_qt);
    rope_kv_kernel<<<dim3(SEQ, NKV), 64>>>(p_kv, p_kt, p_vt);
    // attention
    attn_wmma<<<dim3(SEQ / 64, NH), 256>>>(p_qt, p_kt, p_vt, p_attn);
    // output projection: [S,HDIM] = attn @ o_w^T
    tf32_gemm_nt<<<dim3((HDIM + 127) / 128, MB), 256>>>(p_attn, o_w, out, SEQ, HDIM, QDIM);
    // + o_b
    add_bias_kernel<<<SEQ, 256>>>(out, o_b, HDIM);
}

// round 4
// speedup vs baseline: 1.2479x; 1.0232x over previous
#include <cuda_runtime.h>
#include <cuda_bf16.h>
#include <mma.h>
#include <cstdint>

using namespace nvcuda;

// Problem constants
#define SEQ   2048
#define HDIM  2880
#define NH    64
#define HD    64
#define NKV   8
#define RANK  384
#define QDIM  4096   // NH*HD
#define KVDIM 1024   // NKV*HD*2
#define ROPE_BASE 150000.0f

// ---------------------------------------------------------------------------
// Scratch
// ---------------------------------------------------------------------------
__device__ float g_q   [SEQ * QDIM];
__device__ float g_ckv [SEQ * RANK];
__device__ float g_kv  [SEQ * KVDIM];
__device__ float g_qt  [NH  * SEQ * HD];
__device__ float g_kt  [NKV * SEQ * HD];
__device__ float g_vt  [NKV * SEQ * HD];
__device__ float g_attn[SEQ * QDIM];
// tf32-prerounded operand copies
__device__ float g_h   [SEQ * HDIM];
__device__ float g_qw  [QDIM * HDIM];
__device__ float g_kaw [RANK * HDIM];
__device__ float g_kbw [KVDIM * RANK];
__device__ float g_ow  [HDIM * QDIM];

__device__ __forceinline__ float to_tf32(float x) {
    float r;
    asm("cvt.rna.tf32.f32 %0, %1;" : "=f"(r) : "f"(x));
    return r;
}
__device__ __forceinline__ uint32_t smem_u32(const void* p) {
    uint32_t a;
    asm("{ .reg .u64 t; cvta.to.shared.u64 t, %1; cvt.u32.u64 %0, t; }"
        : "=r"(a) : "l"(p));
    return a;
}
__device__ __forceinline__ void cp_async16(uint32_t dst, const void* src) {
    asm volatile("cp.async.ca.shared.global [%0], [%1], 16;"
                 :: "r"(dst), "l"(src) : "memory");
}
__device__ __forceinline__ void cp_async_commit() {
    asm volatile("cp.async.commit_group;" ::: "memory");
}
__device__ __forceinline__ void cp_async_wait1() {
    asm volatile("cp.async.wait_group 1;" ::: "memory");
}

// ---------------------------------------------------------------------------
// Elementwise tf32 rounding pass (float4 vectorized)
// ---------------------------------------------------------------------------
__global__ void round_tf32_kernel(const float* __restrict__ in,
                                  float* __restrict__ out, int n4) {
    int i = blockIdx.x * blockDim.x + threadIdx.x;
    if (i < n4) {
        float4 v = ((const float4*)in)[i];
        v.x = to_tf32(v.x); v.y = to_tf32(v.y);
        v.z = to_tf32(v.z); v.w = to_tf32(v.w);
        ((float4*)out)[i] = v;
    }
}

// ---------------------------------------------------------------------------
// Pipelined TF32 wmma GEMM: C[M,N] = A[M,K] @ B[N,K]^T
// Inputs must already be tf32-rounded. CTA tile 128x256, BK=16, 3-stage
// cp.async pipeline, 8 warps (2x4), warp tile 64x64.
// ---------------------------------------------------------------------------
#define GLDT 20                         // floats per smem row (16 + 4 pad; 80B, 16B-aligned)
#define GST_A (128 * GLDT)              // A stage floats
#define GST_FLOATS ((128 + 256) * GLDT) // stage floats (7680 -> 30720B)
#define GSTAGES 3
#define GSMEM_BYTES (GSTAGES * GST_FLOATS * 4)   // 92160

__global__ __launch_bounds__(256)
void wgemm_tf32(const float* __restrict__ A, const float* __restrict__ B,
                float* __restrict__ C, int M, int N, int K, int round_out) {
    extern __shared__ float smf[];
    const int tid  = threadIdx.x;
    const int warp = tid >> 5;
    const int wm   = warp >> 2;          // 0..1
    const int wn   = warp & 3;           // 0..3
    const int row0 = blockIdx.y * 128;
    const int col0 = blockIdx.x * 256;
    const int NC   = K >> 4;             // K/16 (all K multiples of 16)

    wmma::fragment<wmma::accumulator, 16, 16, 8, float> acc[4][4];
#pragma unroll
    for (int i = 0; i < 4; i++)
#pragma unroll
        for (int j = 0; j < 4; j++) wmma::fill_fragment(acc[i][j], 0.0f);

    // per-thread fixed load slots
    const int ar = (tid >> 2);           // A rows: tid/4 and +64
    const int ac = (tid & 3) * 4;        // 16B chunk (floats)
    const int br = (tid >> 2);           // B rows: tid/4, +64, +128, +192

    auto issue = [&](int c) {
        float* sa = smf + (c % GSTAGES) * GST_FLOATS;
        float* sb = sa + GST_A;
        const int k0 = c << 4;
#pragma unroll
        for (int i = 0; i < 2; i++) {
            int r = ar + i * 64;
            cp_async16(smem_u32(sa + r * GLDT + ac),
                       A + (size_t)(row0 + r) * K + k0 + ac);
        }
#pragma unroll
        for (int i = 0; i < 4; i++) {
            int r = br + i * 64;
            int gn = col0 + r; if (gn >= N) gn = N - 1;
            cp_async16(smem_u32(sb + r * GLDT + ac),
                       B + (size_t)gn * K + k0 + ac);
        }
    };

    // prologue: stages 0..1
#pragma unroll
    for (int s = 0; s < GSTAGES - 1; s++) {
        issue(s);
        cp_async_commit();
    }

    for (int c = 0; c < NC; c++) {
        cp_async_wait1();      // stage c resident
        __syncthreads();
        if (c + GSTAGES - 1 < NC) issue(c + GSTAGES - 1);
        cp_async_commit();     // keep group accounting uniform

        float* sa = smf + (c % GSTAGES) * GST_FLOATS;
        float* sb = sa + GST_A;
#pragma unroll
        for (int kk = 0; kk < 16; kk += 8) {
            wmma::fragment<wmma::matrix_a, 16, 16, 8, wmma::precision::tf32, wmma::row_major> af[4];
            wmma::fragment<wmma::matrix_b, 16, 16, 8, wmma::precision::tf32, wmma::col_major> bf[4];
#pragma unroll
            for (int i = 0; i < 4; i++)
                wmma::load_matrix_sync(af[i], sa + (wm * 64 + i * 16) * GLDT + kk, GLDT);
#pragma unroll
            for (int j = 0; j < 4; j++)
                wmma::load_matrix_sync(bf[j], sb + (wn * 64 + j * 16) * GLDT + kk, GLDT);
#pragma unroll
            for (int i = 0; i < 4; i++)
#pragma unroll
                for (int j = 0; j < 4; j++)
                    wmma::mma_sync(acc[i][j], af[i], bf[j], acc[i][j]);
        }
        __syncthreads();
    }

    // epilogue
#pragma unroll
    for (int i = 0; i < 4; i++) {
        int gm = row0 + wm * 64 + i * 16;
#pragma unroll
        for (int j = 0; j < 4; j++) {
            int gn = col0 + wn * 64 + j * 16;
            if (gn < N) {
                if (round_out) {
#pragma unroll
                    for (int t = 0; t < acc[i][j].num_elements; t++)
                        acc[i][j].x[t] = to_tf32(acc[i][j].x[t]);
                }
                wmma::store_matrix_sync(C + (size_t)gm * N + gn, acc[i][j], N,
                                        wmma::mem_row_major);
            }
        }
    }
}

// ---------------------------------------------------------------------------
// RoPE (mimics reference fp32 rounding)
// ---------------------------------------------------------------------------
__device__ __forceinline__ void rope_cs(int s, int d, float& c, float& sn) {
    int dd = d & 31;
    float inv = 1.0f / powf(ROPE_BASE, (float)(2 * dd) / 64.0f);
    float ang = (float)s * inv;
    c = cosf(ang);
    sn = sinf(ang);
}

__global__ void rope_q_kernel(const float* __restrict__ q, const float* __restrict__ qb,
                              float* __restrict__ qt) {
    int s = blockIdx.x;
    int t = threadIdx.x;
    int h = blockIdx.y * 4 + (t >> 6);
    int d = t & 63;
    const float* row = q + (size_t)s * QDIM + h * HD;
    const float* brow = qb + h * HD;
    float v = row[d] + brow[d];
    float other = (d < 32) ? -(row[d + 32] + brow[d + 32]) : (row[d - 32] + brow[d - 32]);
    float c, sn; rope_cs(s, d, c, sn);
    qt[((size_t)h * SEQ + s) * HD + d] = v * c + other * sn;
}

__global__ void rope_kv_kernel(const float* __restrict__ kv,
                               float* __restrict__ kt, float* __restrict__ vt) {
    int s = blockIdx.x;
    int kh = blockIdx.y;
    int d = threadIdx.x;
    const float* row = kv + (size_t)s * KVDIM + kh * (2 * HD);
    float kval = row[d];
    float other = (d < 32) ? -row[d + 32] : row[d - 32];
    float c, sn; rope_cs(s, d, c, sn);
    size_t o = ((size_t)kh * SEQ + s) * HD + d;
    kt[o] = kval * c + other * sn;
    vt[o] = row[HD + d];
}

// ---------------------------------------------------------------------------
// Flash attention with TF32 wmma (R1 version; output rounded to tf32 for o-proj)
// ---------------------------------------------------------------------------
__global__ __launch_bounds__(256, 2)
void attn_wmma(const float* __restrict__ qt, const float* __restrict__ kt,
               const float* __restrict__ vt, float* __restrict__ out) {
    __shared__ float qs[64][64];
    __shared__ float ks[64][64];
    __shared__ float vs[64][64];

    const int tid  = threadIdx.x;
    const int warp = tid >> 5;
    const int wm   = warp >> 1;
    const int wn   = warp & 1;
    const int h    = blockIdx.y;
    const int qb   = gridDim.x - 1 - blockIdx.x;
    const int kvh  = h >> 3;

    const float* qbase = qt + ((size_t)h * SEQ + qb * 64) * HD;
    const float* kbase = kt + (size_t)kvh * SEQ * HD;
    const float* vbase = vt + (size_t)kvh * SEQ * HD;

#pragma unroll
    for (int i = 0; i < 4; i++) {
        int idx = tid + i * 256;
        int r = idx >> 4, c4 = (idx & 15) * 4;
        float4 v = *(const float4*)(qbase + r * 64 + c4);
        qs[r][c4 + 0] = to_tf32(v.x); qs[r][c4 + 1] = to_tf32(v.y);
        qs[r][c4 + 2] = to_tf32(v.z); qs[r][c4 + 3] = to_tf32(v.w);
    }

    const int orow = tid >> 2;
    const int oq   = tid & 3;
    float O[16];
#pragma unroll
    for (int c = 0; c < 16; c++) O[c] = 0.f;
    float mrow = -3.0e38f, lrow = 0.f;
    const int gi = qb * 64 + orow;

    __syncthreads();

    for (int jb = 0; jb <= qb; jb++) {
#pragma unroll
        for (int i = 0; i < 4; i++) {
            int idx = tid + i * 256;
            int r = idx >> 4, c4 = (idx & 15) * 4;
            float4 kv4 = *(const float4*)(kbase + ((size_t)jb * 64 + r) * 64 + c4);
            ks[r][c4 + 0] = to_tf32(kv4.x); ks[r][c4 + 1] = to_tf32(kv4.y);
            ks[r][c4 + 2] = to_tf32(kv4.z); ks[r][c4 + 3] = to_tf32(kv4.w);
            float4 vv4 = *(const float4*)(vbase + ((size_t)jb * 64 + r) * 64 + c4);
            vs[r][c4 + 0] = to_tf32(vv4.x); vs[r][c4 + 1] = to_tf32(vv4.y);
            vs[r][c4 + 2] = to_tf32(vv4.z); vs[r][c4 + 3] = to_tf32(vv4.w);
        }
        __syncthreads();

        wmma::fragment<wmma::accumulator, 16, 16, 8, float> sacc[2];
        wmma::fill_fragment(sacc[0], 0.f);
        wmma::fill_fragment(sacc[1], 0.f);
#pragma unroll
        for (int kk = 0; kk < 64; kk += 8) {
            wmma::fragment<wmma::matrix_a, 16, 16, 8, wmma::precision::tf32, wmma::row_major> af;
            wmma::load_matrix_sync(af, &qs[wm * 16][kk], 64);
#pragma unroll
            for (int j = 0; j < 2; j++) {
                wmma::fragment<wmma::matrix_b, 16, 16, 8, wmma::precision::tf32, wmma::col_major> bf;
                wmma::load_matrix_sync(bf, &ks[wn * 32 + j * 16][kk], 64);
                wmma::mma_sync(sacc[j], af, bf, sacc[j]);
            }
        }
        __syncthreads();
#pragma unroll
        for (int j = 0; j < 2; j++)
            wmma::store_matrix_sync(&ks[wm * 16][wn * 32 + j * 16], sacc[j], 64,
                                    wmma::mem_row_major);
        __syncthreads();

        const bool diag = (jb == qb);
        const int gj0 = jb * 64;
        float p[16];
        float lmax = -3.0e38f;
#pragma unroll
        for (int c = 0; c < 16; c++) {
            int j = oq * 16 + c;
            float sv = ks[orow][j] * 0.125f;
            if (diag && (gj0 + j) > gi) sv = -3.0e38f;
            p[c] = sv;
            lmax = fmaxf(lmax, sv);
        }
        lmax = fmaxf(lmax, __shfl_xor_sync(0xffffffffu, lmax, 1));
        lmax = fmaxf(lmax, __shfl_xor_sync(0xffffffffu, lmax, 2));
        float mnew  = fmaxf(mrow, lmax);
        float scale = __expf(mrow - mnew);
        float rs = 0.f;
#pragma unroll
        for (int c = 0; c < 16; c++) {
            p[c] = __expf(p[c] - mnew);
            rs += p[c];
        }
        rs += __shfl_xor_sync(0xffffffffu, rs, 1);
        rs += __shfl_xor_sync(0xffffffffu, rs, 2);
        lrow = lrow * scale + rs;
        mrow = mnew;
#pragma unroll
        for (int c = 0; c < 16; c++) O[c] *= scale;
#pragma unroll
        for (int c = 0; c < 16; c++) ks[orow][oq * 16 + c] = to_tf32(p[c]);
        __syncthreads();

        wmma::fragment<wmma::accumulator, 16, 16, 8, float> pvacc[2];
        wmma::fill_fragment(pvacc[0], 0.f);
        wmma::fill_fragment(pvacc[1], 0.f);
#pragma unroll
        for (int kk = 0; kk < 64; kk += 8) {
            wmma::fragment<wmma::matrix_a, 16, 16, 8, wmma::precision::tf32, wmma::row_major> af;
            wmma::load_matrix_sync(af, &ks[wm * 16][kk], 64);
#pragma unroll
            for (int j = 0; j < 2; j++) {
                wmma::fragment<wmma::matrix_b, 16, 16, 8, wmma::precision::tf32, wmma::row_major> bf;
                wmma::load_matrix_sync(bf, &vs[kk][wn * 32 + j * 16], 64);
                wmma::mma_sync(pvacc[j], af, bf, pvacc[j]);
            }
        }
        __syncthreads();
#pragma unroll
        for (int j = 0; j < 2; j++)
            wmma::store_matrix_sync(&vs[wm * 16][wn * 32 + j * 16], pvacc[j], 64,
                                    wmma::mem_row_major);
        __syncthreads();

#pragma unroll
        for (int c = 0; c < 16; c++) O[c] += vs[orow][oq * 16 + c];
        __syncthreads();
    }

    float inv = 1.0f / lrow;
    size_t row = (size_t)(qb * 64 + orow);
    float* dst = out + row * QDIM + h * HD + oq * 16;
#pragma unroll
    for (int c4 = 0; c4 < 4; c4++) {
        // tf32-round here so the o-proj GEMM can consume raw (matches R2 numerics)
        float4 v = make_float4(to_tf32(O[c4 * 4 + 0] * inv), to_tf32(O[c4 * 4 + 1] * inv),
                               to_tf32(O[c4 * 4 + 2] * inv), to_tf32(O[c4 * 4 + 3] * inv));
        *(float4*)(dst + c4 * 4) = v;
    }
}

// ---------------------------------------------------------------------------
// Bias add for final output
// ---------------------------------------------------------------------------
__global__ void add_bias_kernel(float* __restrict__ C, const float* __restrict__ b, int N) {
    int s = blockIdx.x;
    for (int c4 = threadIdx.x * 4; c4 < N; c4 += blockDim.x * 4) {
        float4 v = *(float4*)(C + (size_t)s * N + c4);
        float4 bb = *(const float4*)(b + c4);
        v.x += bb.x; v.y += bb.y; v.z += bb.z; v.w += bb.w;
        *(float4*)(C + (size_t)s * N + c4) = v;
    }
}

// ---------------------------------------------------------------------------
// Launch
// ---------------------------------------------------------------------------
extern "C" void kernel_launch(void* const* d_in, const int* in_sizes, int n_in,
                              void* d_out, int out_size) {
    const float* hidden = (const float*)d_in[0];
    const float* q_w    = (const float*)d_in[2];
    const float* q_b    = (const float*)d_in[3];
    const float* kv_a_w = (const float*)d_in[4];
    const float* kv_b_w = (const float*)d_in[5];
    const float* o_w    = (const float*)d_in[6];
    const float* o_b    = (const float*)d_in[7];
    float* out = (float*)d_out;

    float *p_q, *p_ckv, *p_kv, *p_qt, *p_kt, *p_vt, *p_attn;
    float *p_h, *p_qw, *p_kaw, *p_kbw, *p_ow;
    cudaGetSymbolAddress((void**)&p_q,    g_q);
    cudaGetSymbolAddress((void**)&p_ckv,  g_ckv);
    cudaGetSymbolAddress((void**)&p_kv,   g_kv);
    cudaGetSymbolAddress((void**)&p_qt,   g_qt);
    cudaGetSymbolAddress((void**)&p_kt,   g_kt);
    cudaGetSymbolAddress((void**)&p_vt,   g_vt);
    cudaGetSymbolAddress((void**)&p_attn, g_attn);
    cudaGetSymbolAddress((void**)&p_h,    g_h);
    cudaGetSymbolAddress((void**)&p_qw,   g_qw);
    cudaGetSymbolAddress((void**)&p_kaw,  g_kaw);
    cudaGetSymbolAddress((void**)&p_kbw,  g_kbw);
    cudaGetSymbolAddress((void**)&p_ow,   g_ow);

    cudaFuncSetAttribute(wgemm_tf32,
                         cudaFuncAttributeMaxDynamicSharedMemorySize, GSMEM_BYTES);

    // tf32 pre-rounding passes
    auto roundN = [&](const float* src, float* dst, int n) {
        int n4 = n / 4;
        round_tf32_kernel<<<(n4 + 255) / 256, 256>>>(src, dst, n4);
    };
    roundN(hidden, p_h,   SEQ * HDIM);
    roundN(q_w,    p_qw,  QDIM * HDIM);
    roundN(kv_a_w, p_kaw, RANK * HDIM);
    roundN(kv_b_w, p_kbw, KVDIM * RANK);
    roundN(o_w,    p_ow,  HDIM * QDIM);

    const int MB = SEQ / 128;   // 16 row tiles

    // q projection: [S,QDIM]
    wgemm_tf32<<<dim3(QDIM / 256, MB), 256, GSMEM_BYTES>>>(
        p_h, p_qw, p_q, SEQ, QDIM, HDIM, 0);
    // compressed kv: [S,RANK] (round output for next GEMM)
    wgemm_tf32<<<dim3((RANK + 255) / 256, MB), 256, GSMEM_BYTES>>>(
        p_h, p_kaw, p_ckv, SEQ, RANK, HDIM, 1);
    // kv expand: [S,KVDIM]
    wgemm_tf32<<<dim3(KVDIM / 256, MB), 256, GSMEM_BYTES>>>(
        p_ckv, p_kbw, p_kv, SEQ, KVDIM, RANK, 0);
    // rope + transpose
    rope_q_kernel<<<dim3(SEQ, NH / 4), 256>>>(p_q, q_b, p_qt);
    rope_kv_kernel<<<dim3(SEQ, NKV), 64>>>(p_kv, p_kt, p_vt);
    // attention
    attn_wmma<<<dim3(SEQ / 64, NH), 256>>>(p_qt, p_kt, p_vt, p_attn);
    // output projection: [S,HDIM]
    wgemm_tf32<<<dim3((HDIM + 255) / 256, MB), 256, GSMEM_BYTES>>>(
        p_attn, p_ow, out, SEQ, HDIM, QDIM, 0);
    // + o_b
    add_bias_kernel<<<SEQ, 256>>>(out, o_b, HDIM);
}

// round 5
// speedup vs baseline: 1.8984x; 1.5213x over previous
#include <cuda_runtime.h>
#include <cuda_bf16.h>
#include <mma.h>
#include <cstdint>

using namespace nvcuda;

// Problem constants
#define SEQ   2048
#define HDIM  2880
#define NH    64
#define HD    64
#define NKV   8
#define RANK  384
#define QDIM  4096   // NH*HD
#define KVDIM 1024   // NKV*HD*2
#define ROPE_BASE 150000.0f

// ---------------------------------------------------------------------------
// Scratch
// ---------------------------------------------------------------------------
__device__ float g_q   [SEQ * QDIM];
__device__ float g_ckv [SEQ * RANK];
__device__ float g_kv  [SEQ * KVDIM];
__device__ float g_qt  [NH  * SEQ * HD];
__device__ float g_kt  [NKV * SEQ * HD];
__device__ float g_vt  [NKV * SEQ * HD];
__device__ float g_attn[SEQ * QDIM];
// tf32-prerounded operand copies
__device__ float g_h   [SEQ * HDIM];
__device__ float g_qw  [QDIM * HDIM];
__device__ float g_kaw [RANK * HDIM];
__device__ float g_kbw [KVDIM * RANK];
__device__ float g_ow  [HDIM * QDIM];

__device__ __forceinline__ float to_tf32(float x) {
    float r;
    asm("cvt.rna.tf32.f32 %0, %1;" : "=f"(r) : "f"(x));
    return r;
}
__device__ __forceinline__ uint32_t smem_u32(const void* p) {
    uint32_t a;
    asm("{ .reg .u64 t; cvta.to.shared.u64 t, %1; cvt.u32.u64 %0, t; }"
        : "=r"(a) : "l"(p));
    return a;
}
__device__ __forceinline__ void cp_async16(uint32_t dst, const void* src) {
    asm volatile("cp.async.ca.shared.global [%0], [%1], 16;"
                 :: "r"(dst), "l"(src) : "memory");
}
__device__ __forceinline__ void cp_async_commit() {
    asm volatile("cp.async.commit_group;" ::: "memory");
}
__device__ __forceinline__ void cp_async_wait1() {
    asm volatile("cp.async.wait_group 1;" ::: "memory");
}

// mma.sync m16n8k8 tf32 (portable, sm_80+)
__device__ __forceinline__ void mma16n8k8(float d[4], const uint32_t a[4],
                                          const uint32_t b[2]) {
    asm volatile(
        "mma.sync.aligned.m16n8k8.row.col.f32.tf32.tf32.f32 "
        "{%0,%1,%2,%3},{%4,%5,%6,%7},{%8,%9},{%0,%1,%2,%3};"
        : "+f"(d[0]), "+f"(d[1]), "+f"(d[2]), "+f"(d[3])
        : "r"(a[0]), "r"(a[1]), "r"(a[2]), "r"(a[3]),
          "r"(b[0]), "r"(b[1]));
}

// ---------------------------------------------------------------------------
// Elementwise tf32 rounding pass (float4 vectorized)
// ---------------------------------------------------------------------------
__global__ void round_tf32_kernel(const float* __restrict__ in,
                                  float* __restrict__ out, int n4) {
    int i = blockIdx.x * blockDim.x + threadIdx.x;
    if (i < n4) {
        float4 v = ((const float4*)in)[i];
        v.x = to_tf32(v.x); v.y = to_tf32(v.y);
        v.z = to_tf32(v.z); v.w = to_tf32(v.w);
        ((float4*)out)[i] = v;
    }
}

// ---------------------------------------------------------------------------
// Pipelined TF32 wmma GEMM (unchanged from R4): C[M,N] = A[M,K] @ B[N,K]^T
// ---------------------------------------------------------------------------
#define GLDT 20
#define GST_A (128 * GLDT)
#define GST_FLOATS ((128 + 256) * GLDT)
#define GSTAGES 3
#define GSMEM_BYTES (GSTAGES * GST_FLOATS * 4)

__global__ __launch_bounds__(256)
void wgemm_tf32(const float* __restrict__ A, const float* __restrict__ B,
                float* __restrict__ C, int M, int N, int K, int round_out) {
    extern __shared__ float smf[];
    const int tid  = threadIdx.x;
    const int warp = tid >> 5;
    const int wm   = warp >> 2;
    const int wn   = warp & 3;
    const int row0 = blockIdx.y * 128;
    const int col0 = blockIdx.x * 256;
    const int NC   = K >> 4;

    wmma::fragment<wmma::accumulator, 16, 16, 8, float> acc[4][4];
#pragma unroll
    for (int i = 0; i < 4; i++)
#pragma unroll
        for (int j = 0; j < 4; j++) wmma::fill_fragment(acc[i][j], 0.0f);

    const int ar = (tid >> 2);
    const int ac = (tid & 3) * 4;
    const int br = (tid >> 2);

    auto issue = [&](int c) {
        float* sa = smf + (c % GSTAGES) * GST_FLOATS;
        float* sb = sa + GST_A;
        const int k0 = c << 4;
#pragma unroll
        for (int i = 0; i < 2; i++) {
            int r = ar + i * 64;
            cp_async16(smem_u32(sa + r * GLDT + ac),
                       A + (size_t)(row0 + r) * K + k0 + ac);
        }
#pragma unroll
        for (int i = 0; i < 4; i++) {
            int r = br + i * 64;
            int gn = col0 + r; if (gn >= N) gn = N - 1;
            cp_async16(smem_u32(sb + r * GLDT + ac),
                       B + (size_t)gn * K + k0 + ac);
        }
    };

#pragma unroll
    for (int s = 0; s < GSTAGES - 1; s++) {
        issue(s);
        cp_async_commit();
    }

    for (int c = 0; c < NC; c++) {
        cp_async_wait1();
        __syncthreads();
        if (c + GSTAGES - 1 < NC) issue(c + GSTAGES - 1);
        cp_async_commit();

        float* sa = smf + (c % GSTAGES) * GST_FLOATS;
        float* sb = sa + GST_A;
#pragma unroll
        for (int kk = 0; kk < 16; kk += 8) {
            wmma::fragment<wmma::matrix_a, 16, 16, 8, wmma::precision::tf32, wmma::row_major> af[4];
            wmma::fragment<wmma::matrix_b, 16, 16, 8, wmma::precision::tf32, wmma::col_major> bf[4];
#pragma unroll
            for (int i = 0; i < 4; i++)
                wmma::load_matrix_sync(af[i], sa + (wm * 64 + i * 16) * GLDT + kk, GLDT);
#pragma unroll
            for (int j = 0; j < 4; j++)
                wmma::load_matrix_sync(bf[j], sb + (wn * 64 + j * 16) * GLDT + kk, GLDT);
#pragma unroll
            for (int i = 0; i < 4; i++)
#pragma unroll
                for (int j = 0; j < 4; j++)
                    wmma::mma_sync(acc[i][j], af[i], bf[j], acc[i][j]);
        }
        __syncthreads();
    }

#pragma unroll
    for (int i = 0; i < 4; i++) {
        int gm = row0 + wm * 64 + i * 16;
#pragma unroll
        for (int j = 0; j < 4; j++) {
            int gn = col0 + wn * 64 + j * 16;
            if (gn < N) {
                if (round_out) {
#pragma unroll
                    for (int t = 0; t < acc[i][j].num_elements; t++)
                        acc[i][j].x[t] = to_tf32(acc[i][j].x[t]);
                }
                wmma::store_matrix_sync(C + (size_t)gm * N + gn, acc[i][j], N,
                                        wmma::mem_row_major);
            }
        }
    }
}

// ---------------------------------------------------------------------------
// RoPE (mimics reference fp32 rounding) — outputs tf32-rounded for attention
// ---------------------------------------------------------------------------
__device__ __forceinline__ void rope_cs(int s, int d, float& c, float& sn) {
    int dd = d & 31;
    float inv = 1.0f / powf(ROPE_BASE, (float)(2 * dd) / 64.0f);
    float ang = (float)s * inv;
    c = cosf(ang);
    sn = sinf(ang);
}

__global__ void rope_q_kernel(const float* __restrict__ q, const float* __restrict__ qb,
                              float* __restrict__ qt) {
    int s = blockIdx.x;
    int t = threadIdx.x;
    int h = blockIdx.y * 4 + (t >> 6);
    int d = t & 63;
    const float* row = q + (size_t)s * QDIM + h * HD;
    const float* brow = qb + h * HD;
    float v = row[d] + brow[d];
    float other = (d < 32) ? -(row[d + 32] + brow[d + 32]) : (row[d - 32] + brow[d - 32]);
    float c, sn; rope_cs(s, d, c, sn);
    qt[((size_t)h * SEQ + s) * HD + d] = to_tf32(v * c + other * sn);
}

__global__ void rope_kv_kernel(const float* __restrict__ kv,
                               float* __restrict__ kt, float* __restrict__ vt) {
    int s = blockIdx.x;
    int kh = blockIdx.y;
    int d = threadIdx.x;
    const float* row = kv + (size_t)s * KVDIM + kh * (2 * HD);
    float kval = row[d];
    float other = (d < 32) ? -row[d + 32] : row[d - 32];
    float c, sn; rope_cs(s, d, c, sn);
    size_t o = ((size_t)kh * SEQ + s) * HD + d;
    kt[o] = to_tf32(kval * c + other * sn);
    vt[o] = to_tf32(row[HD + d]);
}

// ---------------------------------------------------------------------------
// Flash attention, mma.sync m16n8k8 tf32, register-resident O + softmax.
// Block = (head, 128 q rows), 8 warps; warp owns 16 rows.
// K/V streamed in 64-key tiles, 2-stage cp.async double buffer.
// smem floats: Q[128x68] | K0[64x68] V0[64x72] | K1 V1 | P[8 x 16x68]
// ---------------------------------------------------------------------------
#define QLD 68
#define VLD 72
#define AQ_OFF 0
#define AK_OFF 8704                      // 128*68
#define AKV_STRIDE 8960                  // 64*68 + 64*72
#define AP_OFF (AK_OFF + 2 * AKV_STRIDE) // 26624
#define ASMEM_FLOATS (AP_OFF + 8 * 16 * QLD)   // 35328
#define ASMEM_BYTES (ASMEM_FLOATS * 4)         // 141312

__global__ __launch_bounds__(256)
void attn_mma(const float* __restrict__ qt, const float* __restrict__ kt,
              const float* __restrict__ vt, float* __restrict__ out) {
    extern __shared__ float sm[];
    const int tid  = threadIdx.x;
    const int warp = tid >> 5;
    const int lane = tid & 31;
    const int gid  = lane >> 2;          // 0..7 (row in fragment)
    const int q4   = lane & 3;           // 0..3
    const int h    = blockIdx.y;
    const int qb   = gridDim.x - 1 - blockIdx.x;   // long blocks first
    const int kvh  = h >> 3;

    const float* Qg = qt + ((size_t)h * SEQ + qb * 128) * HD;
    const float* Kg = kt + (size_t)kvh * SEQ * HD;
    const float* Vg = vt + (size_t)kvh * SEQ * HD;

    auto issue_kv = [&](int jt, int buf) {
        const float* Kgt = Kg + (size_t)jt * 64 * HD;
        const float* Vgt = Vg + (size_t)jt * 64 * HD;
        float* kb = sm + AK_OFF + buf * AKV_STRIDE;
        float* vb = kb + 64 * QLD;
#pragma unroll
        for (int i = 0; i < 4; i++) {
            int idx = tid + i * 256;          // 0..1023
            int r = idx >> 4, c4 = (idx & 15) * 4;
            cp_async16(smem_u32(kb + r * QLD + c4), Kgt + r * 64 + c4);
            cp_async16(smem_u32(vb + r * VLD + c4), Vgt + r * 64 + c4);
        }
    };

    // prologue: Q + tile 0 in group 0
#pragma unroll
    for (int i = 0; i < 8; i++) {
        int idx = tid + i * 256;              // 0..2047
        int r = idx >> 4, c4 = (idx & 15) * 4;
        cp_async16(smem_u32(sm + r * QLD + c4), Qg + r * 64 + c4);
    }
    issue_kv(0, 0);
    cp_async_commit();

    const int ntiles = 2 * qb + 2;
    const int i0     = qb * 128 + warp * 16 + gid;   // global row of fragment row0
    const int iwmax  = qb * 128 + warp * 16 + 15;

    float m0 = -3.0e38f, m1 = -3.0e38f, l0 = 0.f, l1 = 0.f;
    float O[8][4];
#pragma unroll
    for (int t = 0; t < 8; t++)
#pragma unroll
        for (int e = 0; e < 4; e++) O[t][e] = 0.f;

    float* spw = sm + AP_OFF + warp * (16 * QLD);

    for (int jt = 0; jt < ntiles; jt++) {
        const int buf = jt & 1;
        if (jt + 1 < ntiles) issue_kv(jt + 1, buf ^ 1);
        cp_async_commit();
        cp_async_wait1();
        __syncthreads();

        if (jt * 64 <= iwmax) {
            const float* Kb = sm + AK_OFF + buf * AKV_STRIDE;
            const float* Vb = Kb + 64 * QLD;

            // S = Q @ K^T  (warp: 16 x 64)
            float st[8][4];
#pragma unroll
            for (int t = 0; t < 8; t++)
#pragma unroll
                for (int e = 0; e < 4; e++) st[t][e] = 0.f;

            const float* qrow = sm + (warp * 16 + gid) * QLD + q4;
#pragma unroll
            for (int kk = 0; kk < 8; kk++) {
                uint32_t a[4];
                const float* qp = qrow + kk * 8;
                a[0] = __float_as_uint(qp[0]);
                a[1] = __float_as_uint(qp[8 * QLD]);
                a[2] = __float_as_uint(qp[4]);
                a[3] = __float_as_uint(qp[8 * QLD + 4]);
#pragma unroll
                for (int t = 0; t < 8; t++) {
                    const float* kp = Kb + (t * 8 + gid) * QLD + kk * 8 + q4;
                    uint32_t b[2] = { __float_as_uint(kp[0]), __float_as_uint(kp[4]) };
                    mma16n8k8(st[t], a, b);
                }
            }

            // scale + causal mask + row max
            float mx0 = -3.0e38f, mx1 = -3.0e38f;
            const int jb2 = jt * 64 + 2 * q4;
#pragma unroll
            for (int t = 0; t < 8; t++) {
#pragma unroll
                for (int e = 0; e < 2; e++) {
                    int j = jb2 + t * 8 + e;
                    float v0 = st[t][e] * 0.125f;
                    float v1 = st[t][2 + e] * 0.125f;
                    if (j > i0)     v0 = -3.0e38f;
                    if (j > i0 + 8) v1 = -3.0e38f;
                    st[t][e] = v0; st[t][2 + e] = v1;
                    mx0 = fmaxf(mx0, v0); mx1 = fmaxf(mx1, v1);
                }
            }
            mx0 = fmaxf(mx0, __shfl_xor_sync(0xffffffffu, mx0, 1));
            mx0 = fmaxf(mx0, __shfl_xor_sync(0xffffffffu, mx0, 2));
            mx1 = fmaxf(mx1, __shfl_xor_sync(0xffffffffu, mx1, 1));
            mx1 = fmaxf(mx1, __shfl_xor_sync(0xffffffffu, mx1, 2));

            float mn0 = fmaxf(m0, mx0), mn1 = fmaxf(m1, mx1);
            float sc0 = __expf(m0 - mn0), sc1 = __expf(m1 - mn1);
            m0 = mn0; m1 = mn1;

            float rs0 = 0.f, rs1 = 0.f;
#pragma unroll
            for (int t = 0; t < 8; t++) {
#pragma unroll
                for (int e = 0; e < 2; e++) {
                    float p0 = __expf(st[t][e]     - m0);
                    float p1 = __expf(st[t][2 + e] - m1);
                    st[t][e] = p0; st[t][2 + e] = p1;
                    rs0 += p0; rs1 += p1;
                }
            }
            rs0 += __shfl_xor_sync(0xffffffffu, rs0, 1);
            rs0 += __shfl_xor_sync(0xffffffffu, rs0, 2);
            rs1 += __shfl_xor_sync(0xffffffffu, rs1, 1);
            rs1 += __shfl_xor_sync(0xffffffffu, rs1, 2);
            l0 = l0 * sc0 + rs0;
            l1 = l1 * sc1 + rs1;

#pragma unroll
            for (int t = 0; t < 8; t++) {
                O[t][0] *= sc0; O[t][1] *= sc0;
                O[t][2] *= sc1; O[t][3] *= sc1;
            }

            // stage P (tf32) in per-warp smem strip
#pragma unroll
            for (int t = 0; t < 8; t++) {
                float2 lo = make_float2(to_tf32(st[t][0]), to_tf32(st[t][1]));
                float2 hi = make_float2(to_tf32(st[t][2]), to_tf32(st[t][3]));
                *(float2*)(spw + gid * QLD + t * 8 + 2 * q4) = lo;
                *(float2*)(spw + (gid + 8) * QLD + t * 8 + 2 * q4) = hi;
            }
            __syncwarp();

            // O += P @ V  (warp: 16 x 64)
#pragma unroll
            for (int kk = 0; kk < 8; kk++) {
                uint32_t a[4];
                const float* pp = spw + gid * QLD + kk * 8 + q4;
                a[0] = __float_as_uint(pp[0]);
                a[1] = __float_as_uint(pp[8 * QLD]);
                a[2] = __float_as_uint(pp[4]);
                a[3] = __float_as_uint(pp[8 * QLD + 4]);
#pragma unroll
                for (int t = 0; t < 8; t++) {
                    const float* vp = Vb + (kk * 8 + q4) * VLD + t * 8 + gid;
                    uint32_t b[2] = { __float_as_uint(vp[0]), __float_as_uint(vp[4 * VLD]) };
                    mma16n8k8(O[t], a, b);
                }
            }
        }
        __syncthreads();
    }

    // epilogue: divide by l, tf32-round, write [s][h*64+d]
    float inv0 = 1.0f / l0, inv1 = 1.0f / l1;
    const int r0 = qb * 128 + warp * 16 + gid;
    float* dst0 = out + (size_t)r0 * QDIM + h * HD;
    float* dst1 = dst0 + (size_t)8 * QDIM;
#pragma unroll
    for (int t = 0; t < 8; t++) {
        float2 v0 = make_float2(to_tf32(O[t][0] * inv0), to_tf32(O[t][1] * inv0));
        float2 v1 = make_float2(to_tf32(O[t][2] * inv1), to_tf32(O[t][3] * inv1));
        *(float2*)(dst0 + t * 8 + 2 * q4) = v0;
        *(float2*)(dst1 + t * 8 + 2 * q4) = v1;
    }
}

// ---------------------------------------------------------------------------
// Bias add for final output
// ---------------------------------------------------------------------------
__global__ void add_bias_kernel(float* __restrict__ C, const float* __restrict__ b, int N) {
    int s = blockIdx.x;
    for (int c4 = threadIdx.x * 4; c4 < N; c4 += blockDim.x * 4) {
        float4 v = *(float4*)(C + (size_t)s * N + c4);
        float4 bb = *(const float4*)(b + c4);
        v.x += bb.x; v.y += bb.y; v.z += bb.z; v.w += bb.w;
        *(float4*)(C + (size_t)s * N + c4) = v;
    }
}

// ---------------------------------------------------------------------------
// Launch
// ---------------------------------------------------------------------------
extern "C" void kernel_launch(void* const* d_in, const int* in_sizes, int n_in,
                              void* d_out, int out_size) {
    const float* hidden = (const float*)d_in[0];
    const float* q_w    = (const float*)d_in[2];
    const float* q_b    = (const float*)d_in[3];
    const float* kv_a_w = (const float*)d_in[4];
    const float* kv_b_w = (const float*)d_in[5];
    const float* o_w    = (const float*)d_in[6];
    const float* o_b    = (const float*)d_in[7];
    float* out = (float*)d_out;

    float *p_q, *p_ckv, *p_kv, *p_qt, *p_kt, *p_vt, *p_attn;
    float *p_h, *p_qw, *p_kaw, *p_kbw, *p_ow;
    cudaGetSymbolAddress((void**)&p_q,    g_q);
    cudaGetSymbolAddress((void**)&p_ckv,  g_ckv);
    cudaGetSymbolAddress((void**)&p_kv,   g_kv);
    cudaGetSymbolAddress((void**)&p_qt,   g_qt);
    cudaGetSymbolAddress((void**)&p_kt,   g_kt);
    cudaGetSymbolAddress((void**)&p_vt,   g_vt);
    cudaGetSymbolAddress((void**)&p_attn, g_attn);
    cudaGetSymbolAddress((void**)&p_h,    g_h);
    cudaGetSymbolAddress((void**)&p_qw,   g_qw);
    cudaGetSymbolAddress((void**)&p_kaw,  g_kaw);
    cudaGetSymbolAddress((void**)&p_kbw,  g_kbw);
    cudaGetSymbolAddress((void**)&p_ow,   g_ow);

    cudaFuncSetAttribute(wgemm_tf32,
                         cudaFuncAttributeMaxDynamicSharedMemorySize, GSMEM_BYTES);
    cudaFuncSetAttribute(attn_mma,
                         cudaFuncAttributeMaxDynamicSharedMemorySize, ASMEM_BYTES);

    auto roundN = [&](const float* src, float* dst, int n) {
        int n4 = n / 4;
        round_tf32_kernel<<<(n4 + 255) / 256, 256>>>(src, dst, n4);
    };
    roundN(hidden, p_h,   SEQ * HDIM);
    roundN(q_w,    p_qw,  QDIM * HDIM);
    roundN(kv_a_w, p_kaw, RANK * HDIM);
    roundN(kv_b_w, p_kbw, KVDIM * RANK);
    roundN(o_w,    p_ow,  HDIM * QDIM);

    const int MB = SEQ / 128;   // 16 row tiles

    // q projection
    wgemm_tf32<<<dim3(QDIM / 256, MB), 256, GSMEM_BYTES>>>(
        p_h, p_qw, p_q, SEQ, QDIM, HDIM, 0);
    // compressed kv (round output for next GEMM)
    wgemm_tf32<<<dim3((RANK + 255) / 256, MB), 256, GSMEM_BYTES>>>(
        p_h, p_kaw, p_ckv, SEQ, RANK, HDIM, 1);
    // kv expand
    wgemm_tf32<<<dim3(KVDIM / 256, MB), 256, GSMEM_BYTES>>>(
        p_ckv, p_kbw, p_kv, SEQ, KVDIM, RANK, 0);
    // rope + transpose (tf32-rounded outputs)
    rope_q_kernel<<<dim3(SEQ, NH / 4), 256>>>(p_q, q_b, p_qt);
    rope_kv_kernel<<<dim3(SEQ, NKV), 64>>>(p_kv, p_kt, p_vt);
    // attention (128 q rows per block)
    attn_mma<<<dim3(SEQ / 128, NH), 256, ASMEM_BYTES>>>(p_qt, p_kt, p_vt, p_attn);
    // output projection
    wgemm_tf32<<<dim3((HDIM + 255) / 256, MB), 256, GSMEM_BYTES>>>(
        p_attn, p_ow, out, SEQ, HDIM, QDIM, 0);
    // + o_b
    add_bias_kernel<<<SEQ, 256>>>(out, o_b, HDIM);
}

// round 6
// speedup vs baseline: 1.9168x; 1.0097x over previous
#include <cuda_runtime.h>
#include <cuda_bf16.h>
#include <mma.h>
#include <cstdint>

using namespace nvcuda;

// Problem constants
#define SEQ   2048
#define HDIM  2880
#define NH    64
#define HD    64
#define NKV   8
#define RANK  384
#define QDIM  4096   // NH*HD
#define KVDIM 1024   // NKV*HD*2
#define ROPE_BASE 150000.0f

// ---------------------------------------------------------------------------
// Scratch
// ---------------------------------------------------------------------------
__device__ float g_q   [SEQ * QDIM];
__device__ float g_ckv [SEQ * RANK];
__device__ float g_kv  [SEQ * KVDIM];
__device__ float g_qt  [NH  * SEQ * HD];
__device__ float g_kt  [NKV * SEQ * HD];
__device__ float g_vt  [NKV * SEQ * HD];
__device__ float g_attn[SEQ * QDIM];
// tf32-prerounded operand copies
__device__ float g_h   [SEQ * HDIM];
__device__ float g_qw  [QDIM * HDIM];
__device__ float g_kaw [RANK * HDIM];
__device__ float g_kbw [KVDIM * RANK];
__device__ float g_ow  [HDIM * QDIM];

__device__ __forceinline__ float to_tf32(float x) {
    float r;
    asm("cvt.rna.tf32.f32 %0, %1;" : "=f"(r) : "f"(x));
    return r;
}
__device__ __forceinline__ uint32_t smem_u32(const void* p) {
    uint32_t a;
    asm("{ .reg .u64 t; cvta.to.shared.u64 t, %1; cvt.u32.u64 %0, t; }"
        : "=r"(a) : "l"(p));
    return a;
}
__device__ __forceinline__ void cp_async16(uint32_t dst, const void* src) {
    asm volatile("cp.async.ca.shared.global [%0], [%1], 16;"
                 :: "r"(dst), "l"(src) : "memory");
}
__device__ __forceinline__ void cp_async_commit() {
    asm volatile("cp.async.commit_group;" ::: "memory");
}
__device__ __forceinline__ void cp_async_wait1() {
    asm volatile("cp.async.wait_group 1;" ::: "memory");
}
__device__ __forceinline__ void cp_async_wait0() {
    asm volatile("cp.async.wait_group 0;" ::: "memory");
}

// mma.sync m16n8k8 tf32 (portable, sm_80+)
__device__ __forceinline__ void mma16n8k8(float d[4], const uint32_t a[4],
                                          const uint32_t b[2]) {
    asm volatile(
        "mma.sync.aligned.m16n8k8.row.col.f32.tf32.tf32.f32 "
        "{%0,%1,%2,%3},{%4,%5,%6,%7},{%8,%9},{%0,%1,%2,%3};"
        : "+f"(d[0]), "+f"(d[1]), "+f"(d[2]), "+f"(d[3])
        : "r"(a[0]), "r"(a[1]), "r"(a[2]), "r"(a[3]),
          "r"(b[0]), "r"(b[1]));
}

// ---------------------------------------------------------------------------
// Elementwise tf32 rounding pass (float4 vectorized)
// ---------------------------------------------------------------------------
__global__ void round_tf32_kernel(const float* __restrict__ in,
                                  float* __restrict__ out, int n4) {
    int i = blockIdx.x * blockDim.x + threadIdx.x;
    if (i < n4) {
        float4 v = ((const float4*)in)[i];
        v.x = to_tf32(v.x); v.y = to_tf32(v.y);
        v.z = to_tf32(v.z); v.w = to_tf32(v.w);
        ((float4*)out)[i] = v;
    }
}

// ---------------------------------------------------------------------------
// Pipelined TF32 wmma GEMM (unchanged): C[M,N] = A[M,K] @ B[N,K]^T
// ---------------------------------------------------------------------------
#define GLDT 20
#define GST_A (128 * GLDT)
#define GST_FLOATS ((128 + 256) * GLDT)
#define GSTAGES 3
#define GSMEM_BYTES (GSTAGES * GST_FLOATS * 4)

__global__ __launch_bounds__(256)
void wgemm_tf32(const float* __restrict__ A, const float* __restrict__ B,
                float* __restrict__ C, int M, int N, int K, int round_out) {
    extern __shared__ float smf[];
    const int tid  = threadIdx.x;
    const int warp = tid >> 5;
    const int wm   = warp >> 2;
    const int wn   = warp & 3;
    const int row0 = blockIdx.y * 128;
    const int col0 = blockIdx.x * 256;
    const int NC   = K >> 4;

    wmma::fragment<wmma::accumulator, 16, 16, 8, float> acc[4][4];
#pragma unroll
    for (int i = 0; i < 4; i++)
#pragma unroll
        for (int j = 0; j < 4; j++) wmma::fill_fragment(acc[i][j], 0.0f);

    const int ar = (tid >> 2);
    const int ac = (tid & 3) * 4;
    const int br = (tid >> 2);

    auto issue = [&](int c) {
        float* sa = smf + (c % GSTAGES) * GST_FLOATS;
        float* sb = sa + GST_A;
        const int k0 = c << 4;
#pragma unroll
        for (int i = 0; i < 2; i++) {
            int r = ar + i * 64;
            cp_async16(smem_u32(sa + r * GLDT + ac),
                       A + (size_t)(row0 + r) * K + k0 + ac);
        }
#pragma unroll
        for (int i = 0; i < 4; i++) {
            int r = br + i * 64;
            int gn = col0 + r; if (gn >= N) gn = N - 1;
            cp_async16(smem_u32(sb + r * GLDT + ac),
                       B + (size_t)gn * K + k0 + ac);
        }
    };

#pragma unroll
    for (int s = 0; s < GSTAGES - 1; s++) {
        issue(s);
        cp_async_commit();
    }

    for (int c = 0; c < NC; c++) {
        cp_async_wait1();
        __syncthreads();
        if (c + GSTAGES - 1 < NC) issue(c + GSTAGES - 1);
        cp_async_commit();

        float* sa = smf + (c % GSTAGES) * GST_FLOATS;
        float* sb = sa + GST_A;
#pragma unroll
        for (int kk = 0; kk < 16; kk += 8) {
            wmma::fragment<wmma::matrix_a, 16, 16, 8, wmma::precision::tf32, wmma::row_major> af[4];
            wmma::fragment<wmma::matrix_b, 16, 16, 8, wmma::precision::tf32, wmma::col_major> bf[4];
#pragma unroll
            for (int i = 0; i < 4; i++)
                wmma::load_matrix_sync(af[i], sa + (wm * 64 + i * 16) * GLDT + kk, GLDT);
#pragma unroll
            for (int j = 0; j < 4; j++)
                wmma::load_matrix_sync(bf[j], sb + (wn * 64 + j * 16) * GLDT + kk, GLDT);
#pragma unroll
            for (int i = 0; i < 4; i++)
#pragma unroll
                for (int j = 0; j < 4; j++)
                    wmma::mma_sync(acc[i][j], af[i], bf[j], acc[i][j]);
        }
        __syncthreads();
    }

#pragma unroll
    for (int i = 0; i < 4; i++) {
        int gm = row0 + wm * 64 + i * 16;
#pragma unroll
        for (int j = 0; j < 4; j++) {
            int gn = col0 + wn * 64 + j * 16;
            if (gn < N) {
                if (round_out) {
#pragma unroll
                    for (int t = 0; t < acc[i][j].num_elements; t++)
                        acc[i][j].x[t] = to_tf32(acc[i][j].x[t]);
                }
                wmma::store_matrix_sync(C + (size_t)gm * N + gn, acc[i][j], N,
                                        wmma::mem_row_major);
            }
        }
    }
}

// ---------------------------------------------------------------------------
// RoPE (mimics reference fp32 rounding) — outputs tf32-rounded for attention
// ---------------------------------------------------------------------------
__device__ __forceinline__ void rope_cs(int s, int d, float& c, float& sn) {
    int dd = d & 31;
    float inv = 1.0f / powf(ROPE_BASE, (float)(2 * dd) / 64.0f);
    float ang = (float)s * inv;
    c = cosf(ang);
    sn = sinf(ang);
}

__global__ void rope_q_kernel(const float* __restrict__ q, const float* __restrict__ qb,
                              float* __restrict__ qt) {
    int s = blockIdx.x;
    int t = threadIdx.x;
    int h = blockIdx.y * 4 + (t >> 6);
    int d = t & 63;
    const float* row = q + (size_t)s * QDIM + h * HD;
    const float* brow = qb + h * HD;
    float v = row[d] + brow[d];
    float other = (d < 32) ? -(row[d + 32] + brow[d + 32]) : (row[d - 32] + brow[d - 32]);
    float c, sn; rope_cs(s, d, c, sn);
    qt[((size_t)h * SEQ + s) * HD + d] = to_tf32(v * c + other * sn);
}

__global__ void rope_kv_kernel(const float* __restrict__ kv,
                               float* __restrict__ kt, float* __restrict__ vt) {
    int s = blockIdx.x;
    int kh = blockIdx.y;
    int d = threadIdx.x;
    const float* row = kv + (size_t)s * KVDIM + kh * (2 * HD);
    float kval = row[d];
    float other = (d < 32) ? -row[d + 32] : row[d - 32];
    float c, sn; rope_cs(s, d, c, sn);
    size_t o = ((size_t)kh * SEQ + s) * HD + d;
    kt[o] = to_tf32(kval * c + other * sn);
    vt[o] = to_tf32(row[HD + d]);
}

// ---------------------------------------------------------------------------
// Flash attention v3: mma.sync m16n8k8 tf32.
// - Q lives in registers (a-fragments) for the whole key loop.
// - P accumulator -> A fragment via intra-quad shuffles (no smem round trip).
// - smem = KV double buffer only (71.7KB) -> 2 CTAs/SM.
// Block = (head, 128 q rows), 8 warps; warp owns 16 rows.
// ---------------------------------------------------------------------------
#define QLD 68
#define VLD 72
#define AKV_BUF (64 * QLD + 64 * VLD)        // 8960 floats per stage
#define ASMEM_FLOATS (2 * AKV_BUF)           // 17920
#define ASMEM_BYTES (ASMEM_FLOATS * 4)       // 71680

__global__ __launch_bounds__(256, 2)
void attn_mma(const float* __restrict__ qt, const float* __restrict__ kt,
              const float* __restrict__ vt, float* __restrict__ out) {
    extern __shared__ float sm[];
    const int tid  = threadIdx.x;
    const int warp = tid >> 5;
    const int lane = tid & 31;
    const int gid  = lane >> 2;          // 0..7 (row in fragment)
    const int q4   = lane & 3;           // 0..3
    const int h    = blockIdx.y;
    const int qb   = gridDim.x - 1 - blockIdx.x;   // long blocks first
    const int kvh  = h >> 3;

    const float* Qg = qt + ((size_t)h * SEQ + qb * 128) * HD;
    const float* Kg = kt + (size_t)kvh * SEQ * HD;
    const float* Vg = vt + (size_t)kvh * SEQ * HD;

    // ---- stage Q through smem (buf0 region), load into register fragments ----
#pragma unroll
    for (int i = 0; i < 8; i++) {
        int idx = tid + i * 256;              // 0..2047
        int r = idx >> 4, c4 = (idx & 15) * 4;
        cp_async16(smem_u32(sm + r * QLD + c4), Qg + r * 64 + c4);
    }
    cp_async_commit();
    cp_async_wait0();
    __syncthreads();

    uint32_t qa[8][4];
    {
        const float* qrow = sm + (warp * 16 + gid) * QLD + q4;
#pragma unroll
        for (int kk = 0; kk < 8; kk++) {
            qa[kk][0] = __float_as_uint(qrow[kk * 8]);
            qa[kk][1] = __float_as_uint(qrow[8 * QLD + kk * 8]);
            qa[kk][2] = __float_as_uint(qrow[kk * 8 + 4]);
            qa[kk][3] = __float_as_uint(qrow[8 * QLD + kk * 8 + 4]);
        }
    }
    __syncthreads();   // all warps done reading Q before KV overwrites buf0

    auto issue_kv = [&](int jt, int buf) {
        const float* Kgt = Kg + (size_t)jt * 64 * HD;
        const float* Vgt = Vg + (size_t)jt * 64 * HD;
        float* kb = sm + buf * AKV_BUF;
        float* vb = kb + 64 * QLD;
#pragma unroll
        for (int i = 0; i < 4; i++) {
            int idx = tid + i * 256;          // 0..1023
            int r = idx >> 4, c4 = (idx & 15) * 4;
            cp_async16(smem_u32(kb + r * QLD + c4), Kgt + r * 64 + c4);
            cp_async16(smem_u32(vb + r * VLD + c4), Vgt + r * 64 + c4);
        }
    };

    issue_kv(0, 0);
    cp_async_commit();

    const int ntiles = 2 * qb + 2;
    const int i0     = qb * 128 + warp * 16 + gid;
    const int iwmax  = qb * 128 + warp * 16 + 15;

    float m0 = -3.0e38f, m1 = -3.0e38f, l0 = 0.f, l1 = 0.f;
    float O[8][4];
#pragma unroll
    for (int t = 0; t < 8; t++)
#pragma unroll
        for (int e = 0; e < 4; e++) O[t][e] = 0.f;

    const uint32_t FULL = 0xffffffffu;
    const int qbase = lane & ~3;          // quad base lane
    const int src0  = qbase + (q4 >> 1);
    const int src1  = src0 + 2;
    const bool odd  = q4 & 1;

    for (int jt = 0; jt < ntiles; jt++) {
        const int buf = jt & 1;
        if (jt + 1 < ntiles) issue_kv(jt + 1, buf ^ 1);
        cp_async_commit();
        cp_async_wait1();
        __syncthreads();

        if (jt * 64 <= iwmax) {
            const float* Kb = sm + buf * AKV_BUF;
            const float* Vb = Kb + 64 * QLD;

            // S = Q @ K^T  (warp: 16 x 64), Q from registers
            float st[8][4];
#pragma unroll
            for (int t = 0; t < 8; t++)
#pragma unroll
                for (int e = 0; e < 4; e++) st[t][e] = 0.f;

#pragma unroll
            for (int kk = 0; kk < 8; kk++) {
#pragma unroll
                for (int t = 0; t < 8; t++) {
                    const float* kp = Kb + (t * 8 + gid) * QLD + kk * 8 + q4;
                    uint32_t b[2] = { __float_as_uint(kp[0]), __float_as_uint(kp[4]) };
                    mma16n8k8(st[t], qa[kk], b);
                }
            }

            // scale + causal mask + row max
            float mx0 = -3.0e38f, mx1 = -3.0e38f;
            const int jb2 = jt * 64 + 2 * q4;
#pragma unroll
            for (int t = 0; t < 8; t++) {
#pragma unroll
                for (int e = 0; e < 2; e++) {
                    int j = jb2 + t * 8 + e;
                    float v0 = st[t][e] * 0.125f;
                    float v1 = st[t][2 + e] * 0.125f;
                    if (j > i0)     v0 = -3.0e38f;
                    if (j > i0 + 8) v1 = -3.0e38f;
                    st[t][e] = v0; st[t][2 + e] = v1;
                    mx0 = fmaxf(mx0, v0); mx1 = fmaxf(mx1, v1);
                }
            }
            mx0 = fmaxf(mx0, __shfl_xor_sync(FULL, mx0, 1));
            mx0 = fmaxf(mx0, __shfl_xor_sync(FULL, mx0, 2));
            mx1 = fmaxf(mx1, __shfl_xor_sync(FULL, mx1, 1));
            mx1 = fmaxf(mx1, __shfl_xor_sync(FULL, mx1, 2));

            float mn0 = fmaxf(m0, mx0), mn1 = fmaxf(m1, mx1);
            float sc0 = __expf(m0 - mn0), sc1 = __expf(m1 - mn1);
            m0 = mn0; m1 = mn1;

            float rs0 = 0.f, rs1 = 0.f;
#pragma unroll
            for (int t = 0; t < 8; t++) {
#pragma unroll
                for (int e = 0; e < 2; e++) {
                    float p0 = __expf(st[t][e]     - m0);
                    float p1 = __expf(st[t][2 + e] - m1);
                    st[t][e] = p0; st[t][2 + e] = p1;
                    rs0 += p0; rs1 += p1;
                }
            }
            rs0 += __shfl_xor_sync(FULL, rs0, 1);
            rs0 += __shfl_xor_sync(FULL, rs0, 2);
            rs1 += __shfl_xor_sync(FULL, rs1, 1);
            rs1 += __shfl_xor_sync(FULL, rs1, 2);
            l0 = l0 * sc0 + rs0;
            l1 = l1 * sc1 + rs1;

#pragma unroll
            for (int t = 0; t < 8; t++) {
                O[t][0] *= sc0; O[t][1] *= sc0;
                O[t][2] *= sc1; O[t][3] *= sc1;
                // round P to tf32 for the PV mma (same numerics as before)
                st[t][0] = to_tf32(st[t][0]); st[t][1] = to_tf32(st[t][1]);
                st[t][2] = to_tf32(st[t][2]); st[t][3] = to_tf32(st[t][3]);
            }

            // O += P @ V: A fragment built from st via intra-quad shuffles
#pragma unroll
            for (int kk = 0; kk < 8; kk++) {
                float t00 = __shfl_sync(FULL, st[kk][0], src0);
                float t01 = __shfl_sync(FULL, st[kk][1], src0);
                float t10 = __shfl_sync(FULL, st[kk][2], src0);
                float t11 = __shfl_sync(FULL, st[kk][3], src0);
                float u00 = __shfl_sync(FULL, st[kk][0], src1);
                float u01 = __shfl_sync(FULL, st[kk][1], src1);
                float u10 = __shfl_sync(FULL, st[kk][2], src1);
                float u11 = __shfl_sync(FULL, st[kk][3], src1);
                uint32_t a[4];
                a[0] = __float_as_uint(odd ? t01 : t00);   // P[gid][8kk+q4]
                a[1] = __float_as_uint(odd ? t11 : t10);   // P[gid+8][8kk+q4]
                a[2] = __float_as_uint(odd ? u01 : u00);   // P[gid][8kk+q4+4]
                a[3] = __float_as_uint(odd ? u11 : u10);   // P[gid+8][8kk+q4+4]
#pragma unroll
                for (int t = 0; t < 8; t++) {
                    const float* vp = Vb + (kk * 8 + q4) * VLD + t * 8 + gid;
                    uint32_t b[2] = { __float_as_uint(vp[0]), __float_as_uint(vp[4 * VLD]) };
                    mma16n8k8(O[t], a, b);
                }
            }
        }
        __syncthreads();
    }

    // epilogue: divide by l, tf32-round, write [s][h*64+d]
    float inv0 = 1.0f / l0, inv1 = 1.0f / l1;
    const int r0 = qb * 128 + warp * 16 + gid;
    float* dst0 = out + (size_t)r0 * QDIM + h * HD;
    float* dst1 = dst0 + (size_t)8 * QDIM;
#pragma unroll
    for (int t = 0; t < 8; t++) {
        float2 v0 = make_float2(to_tf32(O[t][0] * inv0), to_tf32(O[t][1] * inv0));
        float2 v1 = make_float2(to_tf32(O[t][2] * inv1), to_tf32(O[t][3] * inv1));
        *(float2*)(dst0 + t * 8 + 2 * q4) = v0;
        *(float2*)(dst1 + t * 8 + 2 * q4) = v1;
    }
}

// ---------------------------------------------------------------------------
// Bias add for final output
// ---------------------------------------------------------------------------
__global__ void add_bias_kernel(float* __restrict__ C, const float* __restrict__ b, int N) {
    int s = blockIdx.x;
    for (int c4 = threadIdx.x * 4; c4 < N; c4 += blockDim.x * 4) {
        float4 v = *(float4*)(C + (size_t)s * N + c4);
        float4 bb = *(const float4*)(b + c4);
        v.x += bb.x; v.y += bb.y; v.z += bb.z; v.w += bb.w;
        *(float4*)(C + (size_t)s * N + c4) = v;
    }
}

// ---------------------------------------------------------------------------
// Launch
// ---------------------------------------------------------------------------
extern "C" void kernel_launch(void* const* d_in, const int* in_sizes, int n_in,
                              void* d_out, int out_size) {
    const float* hidden = (const float*)d_in[0];
    const float* q_w    = (const float*)d_in[2];
    const float* q_b    = (const float*)d_in[3];
    const float* kv_a_w = (const float*)d_in[4];
    const float* kv_b_w = (const float*)d_in[5];
    const float* o_w    = (const float*)d_in[6];
    const float* o_b    = (const float*)d_in[7];
    float* out = (float*)d_out;

    float *p_q, *p_ckv, *p_kv, *p_qt, *p_kt, *p_vt, *p_attn;
    float *p_h, *p_qw, *p_kaw, *p_kbw, *p_ow;
    cudaGetSymbolAddress((void**)&p_q,    g_q);
    cudaGetSymbolAddress((void**)&p_ckv,  g_ckv);
    cudaGetSymbolAddress((void**)&p_kv,   g_kv);
    cudaGetSymbolAddress((void**)&p_qt,   g_qt);
    cudaGetSymbolAddress((void**)&p_kt,   g_kt);
    cudaGetSymbolAddress((void**)&p_vt,   g_vt);
    cudaGetSymbolAddress((void**)&p_attn, g_attn);
    cudaGetSymbolAddress((void**)&p_h,    g_h);
    cudaGetSymbolAddress((void**)&p_qw,   g_qw);
    cudaGetSymbolAddress((void**)&p_kaw,  g_kaw);
    cudaGetSymbolAddress((void**)&p_kbw,  g_kbw);
    cudaGetSymbolAddress((void**)&p_ow,   g_ow);

    cudaFuncSetAttribute(wgemm_tf32,
                         cudaFuncAttributeMaxDynamicSharedMemorySize, GSMEM_BYTES);
    cudaFuncSetAttribute(attn_mma,
                         cudaFuncAttributeMaxDynamicSharedMemorySize, ASMEM_BYTES);

    auto roundN = [&](const float* src, float* dst, int n) {
        int n4 = n / 4;
        round_tf32_kernel<<<(n4 + 255) / 256, 256>>>(src, dst, n4);
    };
    roundN(hidden, p_h,   SEQ * HDIM);
    roundN(q_w,    p_qw,  QDIM * HDIM);
    roundN(kv_a_w, p_kaw, RANK * HDIM);
    roundN(kv_b_w, p_kbw, KVDIM * RANK);
    roundN(o_w,    p_ow,  HDIM * QDIM);

    const int MB = SEQ / 128;   // 16 row tiles

    // q projection
    wgemm_tf32<<<dim3(QDIM / 256, MB), 256, GSMEM_BYTES>>>(
        p_h, p_qw, p_q, SEQ, QDIM, HDIM, 0);
    // compressed kv (round output for next GEMM)
    wgemm_tf32<<<dim3((RANK + 255) / 256, MB), 256, GSMEM_BYTES>>>(
        p_h, p_kaw, p_ckv, SEQ, RANK, HDIM, 1);
    // kv expand
    wgemm_tf32<<<dim3(KVDIM / 256, MB), 256, GSMEM_BYTES>>>(
        p_ckv, p_kbw, p_kv, SEQ, KVDIM, RANK, 0);
    // rope + transpose (tf32-rounded outputs)
    rope_q_kernel<<<dim3(SEQ, NH / 4), 256>>>(p_q, q_b, p_qt);
    rope_kv_kernel<<<dim3(SEQ, NKV), 64>>>(p_kv, p_kt, p_vt);
    // attention (128 q rows per block)
    attn_mma<<<dim3(SEQ / 128, NH), 256, ASMEM_BYTES>>>(p_qt, p_kt, p_vt, p_attn);
    // output projection
    wgemm_tf32<<<dim3((HDIM + 255) / 256, MB), 256, GSMEM_BYTES>>>(
        p_attn, p_ow, out, SEQ, HDIM, QDIM, 0);
    // + o_b
    add_bias_kernel<<<SEQ, 256>>>(out, o_b, HDIM);
}

// round 7
// speedup vs baseline: 2.1127x; 1.1022x over previous
#include <cuda_runtime.h>
#include <cuda_bf16.h>
#include <mma.h>
#include <cstdint>

using namespace nvcuda;

// Problem constants
#define SEQ   2048
#define HDIM  2880
#define NH    64
#define HD    64
#define NKV   8
#define RANK  384
#define QDIM  4096   // NH*HD
#define KVDIM 1024   // NKV*HD*2
#define ROPE_BASE 150000.0f

// ---------------------------------------------------------------------------
// Scratch
// ---------------------------------------------------------------------------
__device__ float g_q   [SEQ * QDIM];
__device__ float g_ckv [SEQ * RANK];
__device__ float g_kv  [SEQ * KVDIM];
__device__ float g_qt  [NH  * SEQ * HD];
__device__ float g_kt  [NKV * SEQ * HD];
__device__ float g_vt  [NKV * SEQ * HD];
__device__ float g_attn[SEQ * QDIM];
// tf32-prerounded operand copies
__device__ float g_h   [SEQ * HDIM];
__device__ float g_qw  [QDIM * HDIM];
__device__ float g_kaw [RANK * HDIM];
__device__ float g_kbw [KVDIM * RANK];
__device__ float g_ow  [HDIM * QDIM];

__device__ __forceinline__ float to_tf32(float x) {
    float r;
    asm("cvt.rna.tf32.f32 %0, %1;" : "=f"(r) : "f"(x));
    return r;
}
__device__ __forceinline__ uint32_t smem_u32(const void* p) {
    uint32_t a;
    asm("{ .reg .u64 t; cvta.to.shared.u64 t, %1; cvt.u32.u64 %0, t; }"
        : "=r"(a) : "l"(p));
    return a;
}
__device__ __forceinline__ void cp_async16(uint32_t dst, const void* src) {
    asm volatile("cp.async.ca.shared.global [%0], [%1], 16;"
                 :: "r"(dst), "l"(src) : "memory");
}
__device__ __forceinline__ void cp_async_commit() {
    asm volatile("cp.async.commit_group;" ::: "memory");
}
__device__ __forceinline__ void cp_async_wait1() {
    asm volatile("cp.async.wait_group 1;" ::: "memory");
}
__device__ __forceinline__ void cp_async_wait0() {
    asm volatile("cp.async.wait_group 0;" ::: "memory");
}

// mma.sync m16n8k8 tf32 (portable, sm_80+)
__device__ __forceinline__ void mma16n8k8(float d[4], const uint32_t a[4],
                                          const uint32_t b[2]) {
    asm volatile(
        "mma.sync.aligned.m16n8k8.row.col.f32.tf32.tf32.f32 "
        "{%0,%1,%2,%3},{%4,%5,%6,%7},{%8,%9},{%0,%1,%2,%3};"
        : "+f"(d[0]), "+f"(d[1]), "+f"(d[2]), "+f"(d[3])
        : "r"(a[0]), "r"(a[1]), "r"(a[2]), "r"(a[3]),
          "r"(b[0]), "r"(b[1]));
}

// ---------------------------------------------------------------------------
// Elementwise tf32 rounding pass (float4 vectorized)
// ---------------------------------------------------------------------------
__global__ void round_tf32_kernel(const float* __restrict__ in,
                                  float* __restrict__ out, int n4) {
    int i = blockIdx.x * blockDim.x + threadIdx.x;
    if (i < n4) {
        float4 v = ((const float4*)in)[i];
        v.x = to_tf32(v.x); v.y = to_tf32(v.y);
        v.z = to_tf32(v.z); v.w = to_tf32(v.w);
        ((float4*)out)[i] = v;
    }
}

// ---------------------------------------------------------------------------
// Pipelined TF32 wmma GEMM: C[M,N] = A[M,K] @ B[N,K]^T
// CTA tile 128x256, BK=32, 2-stage cp.async, 8 warps (2x4), warp tile 64x64.
// ---------------------------------------------------------------------------
#define GLDT 36                           // 32 + 4 pad floats per smem row
#define GST_A (128 * GLDT)                // 4608 floats
#define GST_FLOATS ((128 + 256) * GLDT)   // 13824 floats per stage
#define GSTAGES 2
#define GSMEM_BYTES (GSTAGES * GST_FLOATS * 4)   // 110592

__global__ __launch_bounds__(256)
void wgemm_tf32(const float* __restrict__ A, const float* __restrict__ B,
                float* __restrict__ C, int M, int N, int K, int round_out) {
    extern __shared__ float smf[];
    const int tid  = threadIdx.x;
    const int warp = tid >> 5;
    const int wm   = warp >> 2;
    const int wn   = warp & 3;
    const int row0 = blockIdx.y * 128;
    const int col0 = blockIdx.x * 256;
    const int NC   = K >> 5;              // K/32 (all K multiples of 32)

    wmma::fragment<wmma::accumulator, 16, 16, 8, float> acc[4][4];
#pragma unroll
    for (int i = 0; i < 4; i++)
#pragma unroll
        for (int j = 0; j < 4; j++) wmma::fill_fragment(acc[i][j], 0.0f);

    auto issue = [&](int c) {
        float* sa = smf + (c & 1) * GST_FLOATS;
        float* sb = sa + GST_A;
        const int k0 = c << 5;
        // A tile: 128 x 32 floats = 1024 float4 -> 4 per thread
#pragma unroll
        for (int i = 0; i < 4; i++) {
            int idx = tid + i * 256;
            int r = idx >> 3, c4 = (idx & 7) * 4;
            cp_async16(smem_u32(sa + r * GLDT + c4),
                       A + (size_t)(row0 + r) * K + k0 + c4);
        }
        // B tile: 256 x 32 floats = 2048 float4 -> 8 per thread
#pragma unroll
        for (int i = 0; i < 8; i++) {
            int idx = tid + i * 256;
            int r = idx >> 3, c4 = (idx & 7) * 4;
            int gn = col0 + r; if (gn >= N) gn = N - 1;
            cp_async16(smem_u32(sb + r * GLDT + c4),
                       B + (size_t)gn * K + k0 + c4);
        }
    };

    issue(0);
    cp_async_commit();

    for (int c = 0; c < NC; c++) {
        if (c + 1 < NC) {
            issue(c + 1);
            cp_async_commit();
            cp_async_wait1();
        } else {
            cp_async_wait0();
        }
        __syncthreads();

        float* sa = smf + (c & 1) * GST_FLOATS;
        float* sb = sa + GST_A;
#pragma unroll
        for (int kk = 0; kk < 32; kk += 8) {
            wmma::fragment<wmma::matrix_a, 16, 16, 8, wmma::precision::tf32, wmma::row_major> af[4];
            wmma::fragment<wmma::matrix_b, 16, 16, 8, wmma::precision::tf32, wmma::col_major> bf[4];
#pragma unroll
            for (int i = 0; i < 4; i++)
                wmma::load_matrix_sync(af[i], sa + (wm * 64 + i * 16) * GLDT + kk, GLDT);
#pragma unroll
            for (int j = 0; j < 4; j++)
                wmma::load_matrix_sync(bf[j], sb + (wn * 64 + j * 16) * GLDT + kk, GLDT);
#pragma unroll
            for (int i = 0; i < 4; i++)
#pragma unroll
                for (int j = 0; j < 4; j++)
                    wmma::mma_sync(acc[i][j], af[i], bf[j], acc[i][j]);
        }
        __syncthreads();
    }

#pragma unroll
    for (int i = 0; i < 4; i++) {
        int gm = row0 + wm * 64 + i * 16;
#pragma unroll
        for (int j = 0; j < 4; j++) {
            int gn = col0 + wn * 64 + j * 16;
            if (gn < N) {
                if (round_out) {
#pragma unroll
                    for (int t = 0; t < acc[i][j].num_elements; t++)
                        acc[i][j].x[t] = to_tf32(acc[i][j].x[t]);
                }
                wmma::store_matrix_sync(C + (size_t)gm * N + gn, acc[i][j], N,
                                        wmma::mem_row_major);
            }
        }
    }
}

// ---------------------------------------------------------------------------
// RoPE (mimics reference fp32 rounding) — outputs tf32-rounded for attention
// ---------------------------------------------------------------------------
__device__ __forceinline__ void rope_cs(int s, int d, float& c, float& sn) {
    int dd = d & 31;
    float inv = 1.0f / powf(ROPE_BASE, (float)(2 * dd) / 64.0f);
    float ang = (float)s * inv;
    c = cosf(ang);
    sn = sinf(ang);
}

__global__ void rope_q_kernel(const float* __restrict__ q, const float* __restrict__ qb,
                              float* __restrict__ qt) {
    int s = blockIdx.x;
    int t = threadIdx.x;
    int h = blockIdx.y * 4 + (t >> 6);
    int d = t & 63;
    const float* row = q + (size_t)s * QDIM + h * HD;
    const float* brow = qb + h * HD;
    float v = row[d] + brow[d];
    float other = (d < 32) ? -(row[d + 32] + brow[d + 32]) : (row[d - 32] + brow[d - 32]);
    float c, sn; rope_cs(s, d, c, sn);
    qt[((size_t)h * SEQ + s) * HD + d] = to_tf32(v * c + other * sn);
}

__global__ void rope_kv_kernel(const float* __restrict__ kv,
                               float* __restrict__ kt, float* __restrict__ vt) {
    int s = blockIdx.x;
    int kh = blockIdx.y;
    int d = threadIdx.x;
    const float* row = kv + (size_t)s * KVDIM + kh * (2 * HD);
    float kval = row[d];
    float other = (d < 32) ? -row[d + 32] : row[d - 32];
    float c, sn; rope_cs(s, d, c, sn);
    size_t o = ((size_t)kh * SEQ + s) * HD + d;
    kt[o] = to_tf32(kval * c + other * sn);
    vt[o] = to_tf32(row[HD + d]);
}

// ---------------------------------------------------------------------------
// Flash attention v3 (unchanged from R6): mma.sync m16n8k8 tf32.
// ---------------------------------------------------------------------------
#define QLD 68
#define VLD 72
#define AKV_BUF (64 * QLD + 64 * VLD)        // 8960 floats per stage
#define ASMEM_FLOATS (2 * AKV_BUF)           // 17920
#define ASMEM_BYTES (ASMEM_FLOATS * 4)       // 71680

__global__ __launch_bounds__(256, 2)
void attn_mma(const float* __restrict__ qt, const float* __restrict__ kt,
              const float* __restrict__ vt, float* __restrict__ out) {
    extern __shared__ float sm[];
    const int tid  = threadIdx.x;
    const int warp = tid >> 5;
    const int lane = tid & 31;
    const int gid  = lane >> 2;
    const int q4   = lane & 3;
    const int h    = blockIdx.y;
    const int qb   = gridDim.x - 1 - blockIdx.x;
    const int kvh  = h >> 3;

    const float* Qg = qt + ((size_t)h * SEQ + qb * 128) * HD;
    const float* Kg = kt + (size_t)kvh * SEQ * HD;
    const float* Vg = vt + (size_t)kvh * SEQ * HD;

#pragma unroll
    for (int i = 0; i < 8; i++) {
        int idx = tid + i * 256;
        int r = idx >> 4, c4 = (idx & 15) * 4;
        cp_async16(smem_u32(sm + r * QLD + c4), Qg + r * 64 + c4);
    }
    cp_async_commit();
    cp_async_wait0();
    __syncthreads();

    uint32_t qa[8][4];
    {
        const float* qrow = sm + (warp * 16 + gid) * QLD + q4;
#pragma unroll
        for (int kk = 0; kk < 8; kk++) {
            qa[kk][0] = __float_as_uint(qrow[kk * 8]);
            qa[kk][1] = __float_as_uint(qrow[8 * QLD + kk * 8]);
            qa[kk][2] = __float_as_uint(qrow[kk * 8 + 4]);
            qa[kk][3] = __float_as_uint(qrow[8 * QLD + kk * 8 + 4]);
        }
    }
    __syncthreads();

    auto issue_kv = [&](int jt, int buf) {
        const float* Kgt = Kg + (size_t)jt * 64 * HD;
        const float* Vgt = Vg + (size_t)jt * 64 * HD;
        float* kb = sm + buf * AKV_BUF;
        float* vb = kb + 64 * QLD;
#pragma unroll
        for (int i = 0; i < 4; i++) {
            int idx = tid + i * 256;
            int r = idx >> 4, c4 = (idx & 15) * 4;
            cp_async16(smem_u32(kb + r * QLD + c4), Kgt + r * 64 + c4);
            cp_async16(smem_u32(vb + r * VLD + c4), Vgt + r * 64 + c4);
        }
    };

    issue_kv(0, 0);
    cp_async_commit();

    const int ntiles = 2 * qb + 2;
    const int i0     = qb * 128 + warp * 16 + gid;
    const int iwmax  = qb * 128 + warp * 16 + 15;

    float m0 = -3.0e38f, m1 = -3.0e38f, l0 = 0.f, l1 = 0.f;
    float O[8][4];
#pragma unroll
    for (int t = 0; t < 8; t++)
#pragma unroll
        for (int e = 0; e < 4; e++) O[t][e] = 0.f;

    const uint32_t FULL = 0xffffffffu;
    const int qbase = lane & ~3;
    const int src0  = qbase + (q4 >> 1);
    const int src1  = src0 + 2;
    const bool odd  = q4 & 1;

    for (int jt = 0; jt < ntiles; jt++) {
        const int buf = jt & 1;
        if (jt + 1 < ntiles) issue_kv(jt + 1, buf ^ 1);
        cp_async_commit();
        cp_async_wait1();
        __syncthreads();

        if (jt * 64 <= iwmax) {
            const float* Kb = sm + buf * AKV_BUF;
            const float* Vb = Kb + 64 * QLD;

            float st[8][4];
#pragma unroll
            for (int t = 0; t < 8; t++)
#pragma unroll
                for (int e = 0; e < 4; e++) st[t][e] = 0.f;

#pragma unroll
            for (int kk = 0; kk < 8; kk++) {
#pragma unroll
                for (int t = 0; t < 8; t++) {
                    const float* kp = Kb + (t * 8 + gid) * QLD + kk * 8 + q4;
                    uint32_t b[2] = { __float_as_uint(kp[0]), __float_as_uint(kp[4]) };
                    mma16n8k8(st[t], qa[kk], b);
                }
            }

            float mx0 = -3.0e38f, mx1 = -3.0e38f;
            const int jb2 = jt * 64 + 2 * q4;
#pragma unroll
            for (int t = 0; t < 8; t++) {
#pragma unroll
                for (int e = 0; e < 2; e++) {
                    int j = jb2 + t * 8 + e;
                    float v0 = st[t][e] * 0.125f;
                    float v1 = st[t][2 + e] * 0.125f;
                    if (j > i0)     v0 = -3.0e38f;
                    if (j > i0 + 8) v1 = -3.0e38f;
                    st[t][e] = v0; st[t][2 + e] = v1;
                    mx0 = fmaxf(mx0, v0); mx1 = fmaxf(mx1, v1);
                }
            }
            mx0 = fmaxf(mx0, __shfl_xor_sync(FULL, mx0, 1));
            mx0 = fmaxf(mx0, __shfl_xor_sync(FULL, mx0, 2));
            mx1 = fmaxf(mx1, __shfl_xor_sync(FULL, mx1, 1));
            mx1 = fmaxf(mx1, __shfl_xor_sync(FULL, mx1, 2));

            float mn0 = fmaxf(m0, mx0), mn1 = fmaxf(m1, mx1);
            float sc0 = __expf(m0 - mn0), sc1 = __expf(m1 - mn1);
            m0 = mn0; m1 = mn1;

            float rs0 = 0.f, rs1 = 0.f;
#pragma unroll
            for (int t = 0; t < 8; t++) {
#pragma unroll
                for (int e = 0; e < 2; e++) {
                    float p0 = __expf(st[t][e]     - m0);
                    float p1 = __expf(st[t][2 + e] - m1);
                    st[t][e] = p0; st[t][2 + e] = p1;
                    rs0 += p0; rs1 += p1;
                }
            }
            rs0 += __shfl_xor_sync(FULL, rs0, 1);
            rs0 += __shfl_xor_sync(FULL, rs0, 2);
            rs1 += __shfl_xor_sync(FULL, rs1, 1);
            rs1 += __shfl_xor_sync(FULL, rs1, 2);
            l0 = l0 * sc0 + rs0;
            l1 = l1 * sc1 + rs1;

#pragma unroll
            for (int t = 0; t < 8; t++) {
                O[t][0] *= sc0; O[t][1] *= sc0;
                O[t][2] *= sc1; O[t][3] *= sc1;
                st[t][0] = to_tf32(st[t][0]); st[t][1] = to_tf32(st[t][1]);
                st[t][2] = to_tf32(st[t][2]); st[t][3] = to_tf32(st[t][3]);
            }

#pragma unroll
            for (int kk = 0; kk < 8; kk++) {
                float t00 = __shfl_sync(FULL, st[kk][0], src0);
                float t01 = __shfl_sync(FULL, st[kk][1], src0);
                float t10 = __shfl_sync(FULL, st[kk][2], src0);
                float t11 = __shfl_sync(FULL, st[kk][3], src0);
                float u00 = __shfl_sync(FULL, st[kk][0], src1);
                float u01 = __shfl_sync(FULL, st[kk][1], src1);
                float u10 = __shfl_sync(FULL, st[kk][2], src1);
                float u11 = __shfl_sync(FULL, st[kk][3], src1);
                uint32_t a[4];
                a[0] = __float_as_uint(odd ? t01 : t00);
                a[1] = __float_as_uint(odd ? t11 : t10);
                a[2] = __float_as_uint(odd ? u01 : u00);
                a[3] = __float_as_uint(odd ? u11 : u10);
#pragma unroll
                for (int t = 0; t < 8; t++) {
                    const float* vp = Vb + (kk * 8 + q4) * VLD + t * 8 + gid;
                    uint32_t b[2] = { __float_as_uint(vp[0]), __float_as_uint(vp[4 * VLD]) };
                    mma16n8k8(O[t], a, b);
                }
            }
        }
        __syncthreads();
    }

    float inv0 = 1.0f / l0, inv1 = 1.0f / l1;
    const int r0 = qb * 128 + warp * 16 + gid;
    float* dst0 = out + (size_t)r0 * QDIM + h * HD;
    float* dst1 = dst0 + (size_t)8 * QDIM;
#pragma unroll
    for (int t = 0; t < 8; t++) {
        float2 v0 = make_float2(to_tf32(O[t][0] * inv0), to_tf32(O[t][1] * inv0));
        float2 v1 = make_float2(to_tf32(O[t][2] * inv1), to_tf32(O[t][3] * inv1));
        *(float2*)(dst0 + t * 8 + 2 * q4) = v0;
        *(float2*)(dst1 + t * 8 + 2 * q4) = v1;
    }
}

// ---------------------------------------------------------------------------
// Bias add for final output
// ---------------------------------------------------------------------------
__global__ void add_bias_kernel(float* __restrict__ C, const float* __restrict__ b, int N) {
    int s = blockIdx.x;
    for (int c4 = threadIdx.x * 4; c4 < N; c4 += blockDim.x * 4) {
        float4 v = *(float4*)(C + (size_t)s * N + c4);
        float4 bb = *(const float4*)(b + c4);
        v.x += bb.x; v.y += bb.y; v.z += bb.z; v.w += bb.w;
        *(float4*)(C + (size_t)s * N + c4) = v;
    }
}

// ---------------------------------------------------------------------------
// Launch — ordered so the 4th launch (ncu's capture slot) is the q-proj GEMM
// ---------------------------------------------------------------------------
extern "C" void kernel_launch(void* const* d_in, const int* in_sizes, int n_in,
                              void* d_out, int out_size) {
    const float* hidden = (const float*)d_in[0];
    const float* q_w    = (const float*)d_in[2];
    const float* q_b    = (const float*)d_in[3];
    const float* kv_a_w = (const float*)d_in[4];
    const float* kv_b_w = (const float*)d_in[5];
    const float* o_w    = (const float*)d_in[6];
    const float* o_b    = (const float*)d_in[7];
    float* out = (float*)d_out;

    float *p_q, *p_ckv, *p_kv, *p_qt, *p_kt, *p_vt, *p_attn;
    float *p_h, *p_qw, *p_kaw, *p_kbw, *p_ow;
    cudaGetSymbolAddress((void**)&p_q,    g_q);
    cudaGetSymbolAddress((void**)&p_ckv,  g_ckv);
    cudaGetSymbolAddress((void**)&p_kv,   g_kv);
    cudaGetSymbolAddress((void**)&p_qt,   g_qt);
    cudaGetSymbolAddress((void**)&p_kt,   g_kt);
    cudaGetSymbolAddress((void**)&p_vt,   g_vt);
    cudaGetSymbolAddress((void**)&p_attn, g_attn);
    cudaGetSymbolAddress((void**)&p_h,    g_h);
    cudaGetSymbolAddress((void**)&p_qw,   g_qw);
    cudaGetSymbolAddress((void**)&p_kaw,  g_kaw);
    cudaGetSymbolAddress((void**)&p_kbw,  g_kbw);
    cudaGetSymbolAddress((void**)&p_ow,   g_ow);

    cudaFuncSetAttribute(wgemm_tf32,
                         cudaFuncAttributeMaxDynamicSharedMemorySize, GSMEM_BYTES);
    cudaFuncSetAttribute(attn_mma,
                         cudaFuncAttributeMaxDynamicSharedMemorySize, ASMEM_BYTES);

    auto roundN = [&](const float* src, float* dst, int n) {
        int n4 = n / 4;
        round_tf32_kernel<<<(n4 + 255) / 256, 256>>>(src, dst, n4);
    };

    const int MB = SEQ / 128;   // 16 row tiles

    // launches 0..2: rounding needed by q-proj
    roundN(hidden, p_h,   SEQ * HDIM);                 // 0
    roundN(q_w,    p_qw,  QDIM * HDIM);                // 1
    roundN(kv_a_w, p_kaw, RANK * HDIM);                // 2
    // launch 3 (ncu capture slot): q projection
    wgemm_tf32<<<dim3(QDIM / 256, MB), 256, GSMEM_BYTES>>>(
        p_h, p_qw, p_q, SEQ, QDIM, HDIM, 0);           // 3
    // remaining rounding
    roundN(kv_b_w, p_kbw, KVDIM * RANK);               // 4
    roundN(o_w,    p_ow,  HDIM * QDIM);                // 5
    // compressed kv (round output for next GEMM)
    wgemm_tf32<<<dim3((RANK + 255) / 256, MB), 256, GSMEM_BYTES>>>(
        p_h, p_kaw, p_ckv, SEQ, RANK, HDIM, 1);
    // kv expand
    wgemm_tf32<<<dim3(KVDIM / 256, MB), 256, GSMEM_BYTES>>>(
        p_ckv, p_kbw, p_kv, SEQ, KVDIM, RANK, 0);
    // rope + transpose (tf32-rounded outputs)
    rope_q_kernel<<<dim3(SEQ, NH / 4), 256>>>(p_q, q_b, p_qt);
    rope_kv_kernel<<<dim3(SEQ, NKV), 64>>>(p_kv, p_kt, p_vt);
    // attention
    attn_mma<<<dim3(SEQ / 128, NH), 256, ASMEM_BYTES>>>(p_qt, p_kt, p_vt, p_attn);
    // output projection
    wgemm_tf32<<<dim3((HDIM + 255) / 256, MB), 256, GSMEM_BYTES>>>(
        p_attn, p_ow, out, SEQ, HDIM, QDIM, 0);
    // + o_b
    add_bias_kernel<<<SEQ, 256>>>(out, o_b, HDIM);
}